// round 1
// baseline (speedup 1.0000x reference)
#include <cuda_runtime.h>

// Problem constants (fixed by the dataset)
#define NMAX   50000
#define EMAX   800000
#define FN_DIM 128
#define OUT_D  128
#define DIN    256
#define NVS    256     // [vals | skip] columns
#define NATT   16      // [att1 | att2] columns

// ---------------------------------------------------------------------------
// Device scratch (static globals: allowed; no runtime allocation)
// ---------------------------------------------------------------------------
__device__ float    d_Wvs[DIN * NVS];      // packed [W_m | W_skip]
__device__ float    d_bvs[NVS];
__device__ float    d_Watt[DIN * NATT];    // packed [W_a1 | W_a2]
__device__ float    d_batt[NATT];
__device__ float    d_atte[EMAX * 8];      // gkt edge attention term
__device__ float    d_vs[NMAX * NVS];      // per-node [vals|skip] (reused both passes)
__device__ float    d_att[NMAX * NATT];    // per-node [att1|att2] (reused)
__device__ float    d_hidden1[NMAX * OUT_D]; // cfg_hidden
__device__ int      d_deg[NMAX];
__device__ int      d_off[NMAX + 1];
__device__ int      d_cursor[NMAX];
__device__ int      d_csrcol[EMAX];
__device__ float    d_logits[EMAX * 8];
__device__ unsigned d_rowmax[NMAX * 8];

// Order-preserving float<->uint encode for atomicMax on signed floats
__device__ __forceinline__ unsigned fenc(float f) {
    unsigned u = __float_as_uint(f);
    return (u & 0x80000000u) ? ~u : (u | 0x80000000u);
}
__device__ __forceinline__ float fdec(unsigned u) {
    return (u & 0x80000000u) ? __uint_as_float(u & 0x7FFFFFFFu)
                             : __uint_as_float(~u);
}

// ---------------------------------------------------------------------------
// Pack weights: W_vs = [W_m | W_skip], W_att = [W_a1 | W_a2] (+ biases)
// ---------------------------------------------------------------------------
__global__ void pack_weights_kernel(const float* __restrict__ Wm,  const float* __restrict__ bm,
                                    const float* __restrict__ Wsk, const float* __restrict__ bsk,
                                    const float* __restrict__ Wa1, const float* __restrict__ ba1,
                                    const float* __restrict__ Wa2, const float* __restrict__ ba2) {
    int i = blockIdx.x * blockDim.x + threadIdx.x;
    if (i < DIN * NVS) {
        int k = i >> 8, j = i & 255;
        d_Wvs[i] = (j < 128) ? Wm[k * 128 + j] : Wsk[k * 128 + (j - 128)];
    }
    if (i < DIN * NATT) {
        int k = i >> 4, j = i & 15;
        d_Watt[i] = (j < 8) ? Wa1[k * 8 + j] : Wa2[k * 8 + (j - 8)];
    }
    if (i < NVS)  d_bvs[i]  = (i < 128) ? bm[i] : bsk[i - 128];
    if (i < NATT) d_batt[i] = (i < 8) ? ba1[i] : ba2[i - 8];
}

// ---------------------------------------------------------------------------
// Edge-feature attention: d_atte[e,h] = gkt_edge_fts[e,:] @ W_ae[:,h] + b_ae[h]
// Warp per edge (grid-stride), W_ae fragment kept in registers.
// lane = s*8 + h : lane covers k in [s*32, s*32+32) for head h.
// ---------------------------------------------------------------------------
__global__ void edge_att_kernel(const float* __restrict__ efts,
                                const float* __restrict__ Wae,
                                const float* __restrict__ bae, int E) {
    int lane = threadIdx.x & 31;
    int h = lane & 7, s = lane >> 3;
    float wf[32];
#pragma unroll
    for (int i = 0; i < 32; i++) wf[i] = Wae[(s * 32 + i) * 8 + h];
    float b = bae[h];
    int warp0 = (blockIdx.x * blockDim.x + threadIdx.x) >> 5;
    int nw    = (gridDim.x * blockDim.x) >> 5;
    for (int e = warp0; e < E; e += nw) {
        const float4* p = (const float4*)(efts + (size_t)e * 128 + s * 32);
        float acc = 0.f;
#pragma unroll
        for (int q = 0; q < 8; q++) {
            float4 v = p[q];
            acc += v.x * wf[q * 4 + 0] + v.y * wf[q * 4 + 1]
                 + v.z * wf[q * 4 + 2] + v.w * wf[q * 4 + 3];
        }
        acc += __shfl_xor_sync(0xffffffffu, acc, 8);
        acc += __shfl_xor_sync(0xffffffffu, acc, 16);
        if (lane < 8) d_atte[(size_t)e * 8 + lane] = acc + b;
    }
}

// ---------------------------------------------------------------------------
// Main GEMM: d_vs[M,256] = concat(fts,hid)[M,256] @ d_Wvs[256,256] + d_bvs
// Classic 128x128 tile, BK=8, 256 threads, 8x8 per thread.
// ---------------------------------------------------------------------------
__global__ __launch_bounds__(256, 2)
void gemm_vs_kernel(const float* __restrict__ fts, const float* __restrict__ hid, int M) {
    __shared__ float As[8][128];   // transposed A
    __shared__ float Bs[8][128];
    int t = threadIdx.x;
    int row0 = blockIdx.x * 128, col0 = blockIdx.y * 128;
    int tx = t & 15, ty = t >> 4;
    float acc[8][8];
#pragma unroll
    for (int i = 0; i < 8; i++)
#pragma unroll
        for (int j = 0; j < 8; j++) acc[i][j] = 0.f;

    int arow = t >> 1, ac4 = (t & 1) * 4;
    int brow = t >> 5, bc4 = (t & 31) * 4;

    for (int kb = 0; kb < 256; kb += 8) {
        const float* Z; int zk;
        if (kb < 128) { Z = fts; zk = kb; } else { Z = hid; zk = kb - 128; }
        int gr = row0 + arow;
        float4 a = make_float4(0.f, 0.f, 0.f, 0.f);
        if (gr < M) a = *(const float4*)&Z[(size_t)gr * 128 + zk + ac4];
        As[ac4 + 0][arow] = a.x; As[ac4 + 1][arow] = a.y;
        As[ac4 + 2][arow] = a.z; As[ac4 + 3][arow] = a.w;
        float4 bld = *(const float4*)&d_Wvs[(kb + brow) * 256 + col0 + bc4];
        *(float4*)&Bs[brow][bc4] = bld;
        __syncthreads();
#pragma unroll
        for (int kk = 0; kk < 8; kk++) {
            float4 a0 = *(const float4*)&As[kk][ty * 8];
            float4 a1 = *(const float4*)&As[kk][ty * 8 + 4];
            float4 b0 = *(const float4*)&Bs[kk][tx * 8];
            float4 b1 = *(const float4*)&Bs[kk][tx * 8 + 4];
            float af[8] = {a0.x, a0.y, a0.z, a0.w, a1.x, a1.y, a1.z, a1.w};
            float bf[8] = {b0.x, b0.y, b0.z, b0.w, b1.x, b1.y, b1.z, b1.w};
#pragma unroll
            for (int i = 0; i < 8; i++)
#pragma unroll
                for (int j = 0; j < 8; j++) acc[i][j] += af[i] * bf[j];
        }
        __syncthreads();
    }
#pragma unroll
    for (int i = 0; i < 8; i++) {
        int gr = row0 + ty * 8 + i;
        if (gr < M) {
#pragma unroll
            for (int j = 0; j < 8; j += 4) {
                int gc = col0 + tx * 8 + j;
                float4 o;
                o.x = acc[i][j + 0] + d_bvs[gc + 0];
                o.y = acc[i][j + 1] + d_bvs[gc + 1];
                o.z = acc[i][j + 2] + d_bvs[gc + 2];
                o.w = acc[i][j + 3] + d_bvs[gc + 3];
                *(float4*)&d_vs[(size_t)gr * 256 + gc] = o;
            }
        }
    }
}

// ---------------------------------------------------------------------------
// Attention GEMM: d_att[M,16] = z @ d_Watt + d_batt
// 128-row tile, BK=32, 128 threads, 4x4 per thread (tx over 4 col-groups).
// ---------------------------------------------------------------------------
__global__ __launch_bounds__(128)
void gemm_att_kernel(const float* __restrict__ fts, const float* __restrict__ hid, int M) {
    __shared__ float Zs[128][33];
    __shared__ float Ws[32][16];
    int t = threadIdx.x;
    int tx = t & 3, ty = t >> 2;
    int row0 = blockIdx.x * 128;
    float acc[4][4];
#pragma unroll
    for (int i = 0; i < 4; i++)
#pragma unroll
        for (int j = 0; j < 4; j++) acc[i][j] = 0.f;

    for (int kb = 0; kb < 256; kb += 32) {
        const float* Z; int zk;
        if (kb < 128) { Z = fts; zk = kb; } else { Z = hid; zk = kb - 128; }
#pragma unroll
        for (int q = 0; q < 8; q++) {
            int idx = q * 128 + t;         // float4 id, 1024 total
            int r = idx >> 3, c4 = (idx & 7) * 4;
            int gr = row0 + r;
            float4 a = make_float4(0.f, 0.f, 0.f, 0.f);
            if (gr < M) a = *(const float4*)&Z[(size_t)gr * 128 + zk + c4];
            Zs[r][c4 + 0] = a.x; Zs[r][c4 + 1] = a.y;
            Zs[r][c4 + 2] = a.z; Zs[r][c4 + 3] = a.w;
        }
        {
            int k = t >> 2, j4 = (t & 3) * 4;
            float4 w = *(const float4*)&d_Watt[(kb + k) * 16 + j4];
            *(float4*)&Ws[k][j4] = w;
        }
        __syncthreads();
#pragma unroll
        for (int kk = 0; kk < 32; kk++) {
            float4 bv = *(const float4*)&Ws[kk][tx * 4];
#pragma unroll
            for (int i = 0; i < 4; i++) {
                float a = Zs[ty * 4 + i][kk];
                acc[i][0] += a * bv.x; acc[i][1] += a * bv.y;
                acc[i][2] += a * bv.z; acc[i][3] += a * bv.w;
            }
        }
        __syncthreads();
    }
#pragma unroll
    for (int i = 0; i < 4; i++) {
        int gr = row0 + ty * 4 + i;
        if (gr < M) {
            int j0 = tx * 4;
            float4 o;
            o.x = acc[i][0] + d_batt[j0 + 0];
            o.y = acc[i][1] + d_batt[j0 + 1];
            o.z = acc[i][2] + d_batt[j0 + 2];
            o.w = acc[i][3] + d_batt[j0 + 3];
            *(float4*)&d_att[(size_t)gr * 16 + j0] = o;
        }
    }
}

// ---------------------------------------------------------------------------
// CSR build helpers
// ---------------------------------------------------------------------------
__global__ void zero_init_kernel(int M) {
    int i = blockIdx.x * blockDim.x + threadIdx.x;
    if (i < M) d_deg[i] = 0;
    if (i < M * 8) d_rowmax[i] = 0u;   // sentinel: below any finite fenc()
}

__global__ void count_kernel(const int* __restrict__ idx, int E) {
    int e = blockIdx.x * blockDim.x + threadIdx.x;
    if (e >= E) return;
    int2 rc = ((const int2*)idx)[e];
    atomicAdd(&d_deg[rc.x], 1);
}

// Single-block exclusive scan over d_deg -> d_off / d_cursor (1024 threads)
__global__ void scan_kernel(int n) {
    __shared__ int wsum[32];
    __shared__ int tot_s;
    int t = threadIdx.x, lane = t & 31, wid = t >> 5;
    int carry = 0;
    for (int base = 0; base < n; base += 1024) {
        int i = base + t;
        int x = (i < n) ? d_deg[i] : 0;
        int v = x;
#pragma unroll
        for (int d = 1; d < 32; d <<= 1) {
            int u = __shfl_up_sync(0xffffffffu, v, d);
            if (lane >= d) v += u;
        }
        if (lane == 31) wsum[wid] = v;
        __syncthreads();
        if (wid == 0) {
            int s = wsum[lane];
            int sv = s;
#pragma unroll
            for (int d = 1; d < 32; d <<= 1) {
                int u = __shfl_up_sync(0xffffffffu, sv, d);
                if (lane >= d) sv += u;
            }
            wsum[lane] = sv - s;              // exclusive warp offsets
            if (lane == 31) tot_s = sv;       // chunk total
        }
        __syncthreads();
        int excl = carry + wsum[wid] + (v - x);
        if (i < n) { d_off[i] = excl; d_cursor[i] = excl; }
        carry += tot_s;
        __syncthreads();                       // protect wsum/tot_s reuse
    }
    if (t == 0) d_off[n] = carry;
}

// ---------------------------------------------------------------------------
// Scatter + logits: one thread per edge. Computes leaky-relu logits, writes
// them at the CSR position, records col, atomicMax per (row, head).
// ---------------------------------------------------------------------------
__global__ void scatter_logits_kernel(const int* __restrict__ idx, int E, int use_atte) {
    int e = blockIdx.x * blockDim.x + threadIdx.x;
    if (e >= E) return;
    int2 rc = ((const int2*)idx)[e];
    int row = rc.x, col = rc.y;
    int pos = atomicAdd(&d_cursor[row], 1);
    d_csrcol[pos] = col;
    const float4* pa = (const float4*)&d_att[(size_t)row * 16];
    const float4* pb = (const float4*)&d_att[(size_t)col * 16 + 8];
    float4 a0 = pa[0], a1 = pa[1];
    float4 b0 = pb[0], b1 = pb[1];
    float lg[8] = {a0.x + b0.x, a0.y + b0.y, a0.z + b0.z, a0.w + b0.w,
                   a1.x + b1.x, a1.y + b1.y, a1.z + b1.z, a1.w + b1.w};
    if (use_atte) {
        const float4* pe = (const float4*)&d_atte[(size_t)e * 8];
        float4 e0 = pe[0], e1 = pe[1];
        lg[0] += e0.x; lg[1] += e0.y; lg[2] += e0.z; lg[3] += e0.w;
        lg[4] += e1.x; lg[5] += e1.y; lg[6] += e1.z; lg[7] += e1.w;
    }
#pragma unroll
    for (int h = 0; h < 8; h++) {
        float u = lg[h];
        u = (u > 0.f) ? u : 0.01f * u;     // leaky_relu, slope 0.01
        lg[h] = u;
        atomicMax(&d_rowmax[(size_t)row * 8 + h], fenc(u));
    }
    *(float4*)&d_logits[(size_t)pos * 8]     = make_float4(lg[0], lg[1], lg[2], lg[3]);
    *(float4*)&d_logits[(size_t)pos * 8 + 4] = make_float4(lg[4], lg[5], lg[6], lg[7]);
}

// ---------------------------------------------------------------------------
// Aggregate: warp per row. Softmax-weighted sum of vals[col] + skip, relu.
// lane covers output cols [lane*4, lane*4+4), head = lane/4.
// out[row, c] = relu( (sum_e exp(l_e - mx)*vals[col_e, c]) / (sum_e exp(...)) + skip[row, c] )
// ---------------------------------------------------------------------------
__global__ __launch_bounds__(256)
void aggregate_kernel(float* __restrict__ outp, int M) {
    int warp = (blockIdx.x * blockDim.x + threadIdx.x) >> 5;
    if (warp >= M) return;
    int lane = threadIdx.x & 31;
    int c0 = lane * 4;
    int h = lane >> 2;
    float mx = fdec(d_rowmax[(size_t)warp * 8 + h]);
    int p = d_off[warp], pend = d_off[warp + 1];
    float s = 0.f;
    float4 acc = make_float4(0.f, 0.f, 0.f, 0.f);
    for (; p < pend; ++p) {
        int col = d_csrcol[p];
        float w = __expf(d_logits[(size_t)p * 8 + h] - mx);
        float4 v = *(const float4*)&d_vs[(size_t)col * 256 + c0];
        s += w;
        acc.x += w * v.x; acc.y += w * v.y; acc.z += w * v.z; acc.w += w * v.w;
    }
    float4 sk = *(const float4*)&d_vs[(size_t)warp * 256 + 128 + c0];
    float inv = (s > 0.f) ? (1.f / s) : 0.f;
    float4 o;
    o.x = fmaxf(acc.x * inv + sk.x, 0.f);
    o.y = fmaxf(acc.y * inv + sk.y, 0.f);
    o.z = fmaxf(acc.z * inv + sk.z, 0.f);
    o.w = fmaxf(acc.w * inv + sk.w, 0.f);
    *(float4*)&outp[(size_t)warp * 128 + c0] = o;
}

// ---------------------------------------------------------------------------
// Launch
// ---------------------------------------------------------------------------
extern "C" void kernel_launch(void* const* d_in, const int* in_sizes, int n_in,
                              void* d_out, int out_size) {
    const float* node_fts = (const float*)d_in[0];
    const float* gkt_efts = (const float*)d_in[1];
    const float* hidden   = (const float*)d_in[2];
    const int*   cfg_idx  = (const int*)d_in[3];
    const int*   gkt_idx  = (const int*)d_in[4];
    const float* W_m    = (const float*)d_in[5];
    const float* b_m    = (const float*)d_in[6];
    const float* W_skip = (const float*)d_in[7];
    const float* b_skip = (const float*)d_in[8];
    const float* W_a1   = (const float*)d_in[9];
    const float* b_a1   = (const float*)d_in[10];
    const float* W_a2   = (const float*)d_in[11];
    const float* b_a2   = (const float*)d_in[12];
    const float* W_ae   = (const float*)d_in[13];
    const float* b_ae   = (const float*)d_in[14];
    float* out = (float*)d_out;

    int M  = in_sizes[0] / 128;
    int Ec = in_sizes[3] / 2;
    int Eg = in_sizes[4] / 2;

    float* hid1 = nullptr;
    cudaGetSymbolAddress((void**)&hid1, d_hidden1);

    pack_weights_kernel<<<(DIN * NVS + 255) / 256, 256>>>(W_m, b_m, W_skip, b_skip,
                                                          W_a1, b_a1, W_a2, b_a2);
    edge_att_kernel<<<2048, 256>>>(gkt_efts, W_ae, b_ae, Eg);

    dim3 ggrid((M + 127) / 128, 2);

    // ---- pass 1 (cfg) ----
    gemm_vs_kernel<<<ggrid, 256>>>(node_fts, hidden, M);
    gemm_att_kernel<<<(M + 127) / 128, 128>>>(node_fts, hidden, M);
    zero_init_kernel<<<(M * 8 + 255) / 256, 256>>>(M);
    count_kernel<<<(Ec + 255) / 256, 256>>>(cfg_idx, Ec);
    scan_kernel<<<1, 1024>>>(M);
    scatter_logits_kernel<<<(Ec + 255) / 256, 256>>>(cfg_idx, Ec, 0);
    aggregate_kernel<<<(M + 7) / 8, 256>>>(hid1, M);

    // ---- pass 2 (gkt) ----
    gemm_vs_kernel<<<ggrid, 256>>>(node_fts, hid1, M);
    gemm_att_kernel<<<(M + 127) / 128, 128>>>(node_fts, hid1, M);
    zero_init_kernel<<<(M * 8 + 255) / 256, 256>>>(M);
    count_kernel<<<(Eg + 255) / 256, 256>>>(gkt_idx, Eg);
    scan_kernel<<<1, 1024>>>(M);
    scatter_logits_kernel<<<(Eg + 255) / 256, 256>>>(gkt_idx, Eg, 1);
    aggregate_kernel<<<(M + 7) / 8, 256>>>(out, M);
}

// round 3
// speedup vs baseline: 1.2472x; 1.2472x over previous
#include <cuda_runtime.h>
#include <cuda_bf16.h>
#include <cstdint>

// Problem constants (fixed by the dataset)
#define NMAX   50000
#define EMAX   800000
#define OUT_D  128
#define DIN    256
#define NVS    256     // [vals | skip] columns
#define NATT   16      // [att1 | att2] columns

// ---------------------------------------------------------------------------
// Device scratch (static globals: allowed; no runtime allocation)
// ---------------------------------------------------------------------------
__device__ float    d_bvs[NVS];
__device__ float    d_Watt[DIN * NATT];    // packed [W_a1 | W_a2]
__device__ float    d_batt[NATT];
__device__ float    d_atte[EMAX * 8];      // gkt edge attention term
__device__ float    d_vs[NMAX * NVS];      // per-node [vals|skip]
__device__ float    d_att[NMAX * NATT];    // per-node [att1|att2]
__device__ float    d_hidden1[NMAX * OUT_D];
__device__ int      d_deg[NMAX];
__device__ int      d_off[NMAX + 1];
__device__ int      d_cursor[NMAX];
__device__ int      d_csrcol[EMAX];
__device__ float    d_logits[EMAX * 8];
__device__ unsigned d_rowmax[NMAX * 8];

// split-bf16 operands for the tensor-core GEMM
__device__ __nv_bfloat16 d_zhi[NMAX * DIN];      // z = [fts | hid], hi part
__device__ __nv_bfloat16 d_zlo[NMAX * DIN];      // lo part
__device__ __nv_bfloat16 d_Wbhi[NVS * DIN];      // B[n][k] = Wvs[k][n], hi
__device__ __nv_bfloat16 d_Wblo[NVS * DIN];      // lo

// ---------------------------------------------------------------------------
// Helpers
// ---------------------------------------------------------------------------
__device__ __forceinline__ uint32_t smem_u32(const void* p) {
    uint32_t a;
    asm("{ .reg .u64 t; cvta.to.shared.u64 t, %1; cvt.u32.u64 %0, t; }" : "=r"(a) : "l"(p));
    return a;
}

__device__ __forceinline__ void ldsm4(uint32_t* r, uint32_t addr) {
    asm volatile("ldmatrix.sync.aligned.m8n8.x4.shared.b16 {%0,%1,%2,%3}, [%4];"
                 : "=r"(r[0]), "=r"(r[1]), "=r"(r[2]), "=r"(r[3]) : "r"(addr));
}

__device__ __forceinline__ void mma16816(float* c, const uint32_t* a, uint32_t b0, uint32_t b1) {
    asm volatile("mma.sync.aligned.m16n8k16.row.col.f32.bf16.bf16.f32 "
                 "{%0,%1,%2,%3}, {%4,%5,%6,%7}, {%8,%9}, {%0,%1,%2,%3};"
                 : "+f"(c[0]), "+f"(c[1]), "+f"(c[2]), "+f"(c[3])
                 : "r"(a[0]), "r"(a[1]), "r"(a[2]), "r"(a[3]), "r"(b0), "r"(b1));
}

// Order-preserving float<->uint encode for atomicMax on signed floats
__device__ __forceinline__ unsigned fenc(float f) {
    unsigned u = __float_as_uint(f);
    return (u & 0x80000000u) ? ~u : (u | 0x80000000u);
}
__device__ __forceinline__ float fdec(unsigned u) {
    return (u & 0x80000000u) ? __uint_as_float(u & 0x7FFFFFFFu)
                             : __uint_as_float(~u);
}

// ---------------------------------------------------------------------------
// Weight prep
// ---------------------------------------------------------------------------
__global__ void pack_weights_kernel(const float* __restrict__ bm, const float* __restrict__ bsk,
                                    const float* __restrict__ Wa1, const float* __restrict__ ba1,
                                    const float* __restrict__ Wa2, const float* __restrict__ ba2) {
    int i = blockIdx.x * blockDim.x + threadIdx.x;
    if (i < DIN * NATT) {
        int k = i >> 4, j = i & 15;
        d_Watt[i] = (j < 8) ? Wa1[k * 8 + j] : Wa2[k * 8 + (j - 8)];
    }
    if (i < NVS)  d_bvs[i]  = (i < 128) ? bm[i] : bsk[i - 128];
    if (i < NATT) d_batt[i] = (i < 8) ? ba1[i] : ba2[i - 8];
}

// B[n][k] = W[k][n] split to bf16 hi/lo
__global__ void pack_weights_bf16_kernel(const float* __restrict__ Wm,
                                         const float* __restrict__ Wsk) {
    int i = blockIdx.x * blockDim.x + threadIdx.x;     // i = n*256 + k
    if (i >= NVS * DIN) return;
    int n = i >> 8, k = i & 255;
    float w = (n < 128) ? Wm[k * 128 + n] : Wsk[k * 128 + (n - 128)];
    __nv_bfloat16 hi = __float2bfloat16(w);
    __nv_bfloat16 lo = __float2bfloat16(w - __bfloat162float(hi));
    d_Wbhi[i] = hi;
    d_Wblo[i] = lo;
}

// Convert a 128-wide fp32 node array into half of z (hi/lo split).
__global__ void convert_half_kernel(const float* __restrict__ src, int M, int half_off) {
    int idx = blockIdx.x * blockDim.x + threadIdx.x;   // one float4 group
    if (idx >= M * 32) return;
    int row = idx >> 5, c4 = (idx & 31) * 4;
    float4 v = *(const float4*)&src[(size_t)row * 128 + c4];
    __nv_bfloat16 h[4], l[4];
    float f[4] = {v.x, v.y, v.z, v.w};
#pragma unroll
    for (int j = 0; j < 4; j++) {
        h[j] = __float2bfloat16(f[j]);
        l[j] = __float2bfloat16(f[j] - __bfloat162float(h[j]));
    }
    size_t o = (size_t)row * 256 + half_off + c4;
    *(uint2*)&d_zhi[o] = *(uint2*)h;
    *(uint2*)&d_zlo[o] = *(uint2*)l;
}

// ---------------------------------------------------------------------------
// Tensor GEMM via mma.sync (HMMA): d_vs[M,256] = z @ Wvs + bias, split-bf16.
// CTA tile 128x128 (grid.y picks 128-col half), 256 threads = 2x4 warps,
// warp tile 64x32. BK=64, 4 chunks. SMEM rows padded to 72 halves (144 B).
// ---------------------------------------------------------------------------
#define SSTR 72                     // halves per smem row
#define SROWB (SSTR * 2)            // 144 bytes
#define OFF_AHI 0
#define OFF_ALO (128 * SROWB)
#define OFF_BHI (2 * 128 * SROWB)
#define OFF_BLO (3 * 128 * SROWB)
#define GEMM_SMEM (4 * 128 * SROWB) // 73728 B

__global__ __launch_bounds__(256, 1)
void gemm_vs_mma_kernel(int M) {
    extern __shared__ char smem[];
    uint32_t sb = smem_u32(smem);
    int t = threadIdx.x, wid = t >> 5, lane = t & 31;
    int warp_m = wid & 1, warp_n = wid >> 1;
    int row0 = blockIdx.x * 128, col0 = blockIdx.y * 128;

    float acc[4][4][4];
#pragma unroll
    for (int a = 0; a < 4; a++)
#pragma unroll
        for (int b = 0; b < 4; b++)
#pragma unroll
            for (int c = 0; c < 4; c++) acc[a][b][c] = 0.f;

    // ldmatrix lane addressing (same pattern for A and B x4 loads)
    int lrow = lane & 15;            // row within 16
    int lcol = (lane >> 4) * 8;      // 0 or 8 halves

    for (int kc = 0; kc < 4; kc++) {
        if (kc) __syncthreads();
        // ---- load chunk: A(hi,lo) 128x64 from z, B(hi,lo) 128x64 from W ----
        int kbase = kc * 64;
#pragma unroll
        for (int i = 0; i < 4; i++) {
            int idx = t + i * 256;           // 1024 uint4 groups per tile
            int r = idx >> 3, k8 = (idx & 7) * 8;
            int grow = row0 + r;
            uint4 ahi = make_uint4(0, 0, 0, 0), alo = ahi;
            if (grow < M) {
                ahi = *(const uint4*)&d_zhi[(size_t)grow * 256 + kbase + k8];
                alo = *(const uint4*)&d_zlo[(size_t)grow * 256 + kbase + k8];
            }
            *(uint4*)(smem + OFF_AHI + r * SROWB + k8 * 2) = ahi;
            *(uint4*)(smem + OFF_ALO + r * SROWB + k8 * 2) = alo;
            int n = col0 + r;
            *(uint4*)(smem + OFF_BHI + r * SROWB + k8 * 2) =
                *(const uint4*)&d_Wbhi[(size_t)n * 256 + kbase + k8];
            *(uint4*)(smem + OFF_BLO + r * SROWB + k8 * 2) =
                *(const uint4*)&d_Wblo[(size_t)n * 256 + kbase + k8];
        }
        __syncthreads();

#pragma unroll
        for (int ks = 0; ks < 4; ks++) {
            int kofs = (ks * 16 + lcol) * 2;
            uint32_t ahi[4][4], alo[4][4];
#pragma unroll
            for (int mi = 0; mi < 4; mi++) {
                uint32_t arow = (uint32_t)(warp_m * 64 + mi * 16 + lrow);
                ldsm4(ahi[mi], sb + OFF_AHI + arow * SROWB + kofs);
                ldsm4(alo[mi], sb + OFF_ALO + arow * SROWB + kofs);
            }
            uint32_t bhi[2][4], blo[2][4];
#pragma unroll
            for (int nj = 0; nj < 2; nj++) {
                uint32_t brow = (uint32_t)(warp_n * 32 + nj * 16 + lrow);
                ldsm4(bhi[nj], sb + OFF_BHI + brow * SROWB + kofs);
                ldsm4(blo[nj], sb + OFF_BLO + brow * SROWB + kofs);
            }
#pragma unroll
            for (int mi = 0; mi < 4; mi++) {
#pragma unroll
                for (int ni = 0; ni < 4; ni++) {
                    int nj = ni >> 1, pr = ni & 1;
                    uint32_t bh0 = bhi[nj][pr], bh1 = bhi[nj][pr + 2];
                    uint32_t bl0 = blo[nj][pr], bl1 = blo[nj][pr + 2];
                    mma16816(acc[mi][ni], ahi[mi], bh0, bh1);  // hi*hi
                    mma16816(acc[mi][ni], ahi[mi], bl0, bl1);  // hi*lo
                    mma16816(acc[mi][ni], alo[mi], bh0, bh1);  // lo*hi
                }
            }
        }
    }

    // ---- epilogue: c0,c1 -> row (lane>>2); c2,c3 -> row+8; cols (lane&3)*2 ----
#pragma unroll
    for (int mi = 0; mi < 4; mi++) {
        int rA = row0 + warp_m * 64 + mi * 16 + (lane >> 2);
        int rB = rA + 8;
#pragma unroll
        for (int ni = 0; ni < 4; ni++) {
            int col = col0 + warp_n * 32 + ni * 8 + (lane & 3) * 2;
            float2 bias = *(const float2*)&d_bvs[col];
            if (rA < M) {
                float2 o = make_float2(acc[mi][ni][0] + bias.x, acc[mi][ni][1] + bias.y);
                *(float2*)&d_vs[(size_t)rA * 256 + col] = o;
            }
            if (rB < M) {
                float2 o = make_float2(acc[mi][ni][2] + bias.x, acc[mi][ni][3] + bias.y);
                *(float2*)&d_vs[(size_t)rB * 256 + col] = o;
            }
        }
    }
}

// ---------------------------------------------------------------------------
// Edge-feature attention: d_atte[e,h] = gkt_edge_fts[e,:] @ W_ae[:,h] + b_ae[h]
// ---------------------------------------------------------------------------
__global__ void edge_att_kernel(const float* __restrict__ efts,
                                const float* __restrict__ Wae,
                                const float* __restrict__ bae, int E) {
    int lane = threadIdx.x & 31;
    int h = lane & 7, s = lane >> 3;
    float wf[32];
#pragma unroll
    for (int i = 0; i < 32; i++) wf[i] = Wae[(s * 32 + i) * 8 + h];
    float b = bae[h];
    int warp0 = (blockIdx.x * blockDim.x + threadIdx.x) >> 5;
    int nw    = (gridDim.x * blockDim.x) >> 5;
    for (int e = warp0; e < E; e += nw) {
        const float4* p = (const float4*)(efts + (size_t)e * 128 + s * 32);
        float acc = 0.f;
#pragma unroll
        for (int q = 0; q < 8; q++) {
            float4 v = p[q];
            acc += v.x * wf[q * 4 + 0] + v.y * wf[q * 4 + 1]
                 + v.z * wf[q * 4 + 2] + v.w * wf[q * 4 + 3];
        }
        acc += __shfl_xor_sync(0xffffffffu, acc, 8);
        acc += __shfl_xor_sync(0xffffffffu, acc, 16);
        if (lane < 8) d_atte[(size_t)e * 8 + lane] = acc + b;
    }
}

// ---------------------------------------------------------------------------
// Attention GEMM (small): d_att[M,16] = z @ d_Watt + d_batt  (SIMT)
// ---------------------------------------------------------------------------
__global__ __launch_bounds__(128)
void gemm_att_kernel(const float* __restrict__ fts, const float* __restrict__ hid, int M) {
    __shared__ float Zs[128][33];
    __shared__ float Ws[32][16];
    int t = threadIdx.x;
    int tx = t & 3, ty = t >> 2;
    int row0 = blockIdx.x * 128;
    float acc[4][4];
#pragma unroll
    for (int i = 0; i < 4; i++)
#pragma unroll
        for (int j = 0; j < 4; j++) acc[i][j] = 0.f;

    for (int kb = 0; kb < 256; kb += 32) {
        const float* Z; int zk;
        if (kb < 128) { Z = fts; zk = kb; } else { Z = hid; zk = kb - 128; }
#pragma unroll
        for (int q = 0; q < 8; q++) {
            int idx = q * 128 + t;
            int r = idx >> 3, c4 = (idx & 7) * 4;
            int gr = row0 + r;
            float4 a = make_float4(0.f, 0.f, 0.f, 0.f);
            if (gr < M) a = *(const float4*)&Z[(size_t)gr * 128 + zk + c4];
            Zs[r][c4 + 0] = a.x; Zs[r][c4 + 1] = a.y;
            Zs[r][c4 + 2] = a.z; Zs[r][c4 + 3] = a.w;
        }
        {
            int k = t >> 2, j4 = (t & 3) * 4;
            float4 w = *(const float4*)&d_Watt[(kb + k) * 16 + j4];
            *(float4*)&Ws[k][j4] = w;
        }
        __syncthreads();
#pragma unroll
        for (int kk = 0; kk < 32; kk++) {
            float4 bv = *(const float4*)&Ws[kk][tx * 4];
#pragma unroll
            for (int i = 0; i < 4; i++) {
                float a = Zs[ty * 4 + i][kk];
                acc[i][0] += a * bv.x; acc[i][1] += a * bv.y;
                acc[i][2] += a * bv.z; acc[i][3] += a * bv.w;
            }
        }
        __syncthreads();
    }
#pragma unroll
    for (int i = 0; i < 4; i++) {
        int gr = row0 + ty * 4 + i;
        if (gr < M) {
            int j0 = tx * 4;
            float4 o;
            o.x = acc[i][0] + d_batt[j0 + 0];
            o.y = acc[i][1] + d_batt[j0 + 1];
            o.z = acc[i][2] + d_batt[j0 + 2];
            o.w = acc[i][3] + d_batt[j0 + 3];
            *(float4*)&d_att[(size_t)gr * 16 + j0] = o;
        }
    }
}

// ---------------------------------------------------------------------------
// CSR build helpers
// ---------------------------------------------------------------------------
__global__ void zero_init_kernel(int M) {
    int i = blockIdx.x * blockDim.x + threadIdx.x;
    if (i < M) d_deg[i] = 0;
    if (i < M * 8) d_rowmax[i] = 0u;
}

__global__ void count_kernel(const int* __restrict__ idx, int E) {
    int e = blockIdx.x * blockDim.x + threadIdx.x;
    if (e >= E) return;
    int2 rc = ((const int2*)idx)[e];
    atomicAdd(&d_deg[rc.x], 1);
}

__global__ void scan_kernel(int n) {
    __shared__ int wsum[32];
    __shared__ int tot_s;
    int t = threadIdx.x, lane = t & 31, wid = t >> 5;
    int carry = 0;
    for (int base = 0; base < n; base += 1024) {
        int i = base + t;
        int x = (i < n) ? d_deg[i] : 0;
        int v = x;
#pragma unroll
        for (int d = 1; d < 32; d <<= 1) {
            int u = __shfl_up_sync(0xffffffffu, v, d);
            if (lane >= d) v += u;
        }
        if (lane == 31) wsum[wid] = v;
        __syncthreads();
        if (wid == 0) {
            int s = wsum[lane];
            int sv = s;
#pragma unroll
            for (int d = 1; d < 32; d <<= 1) {
                int u = __shfl_up_sync(0xffffffffu, sv, d);
                if (lane >= d) sv += u;
            }
            wsum[lane] = sv - s;
            if (lane == 31) tot_s = sv;
        }
        __syncthreads();
        int excl = carry + wsum[wid] + (v - x);
        if (i < n) { d_off[i] = excl; d_cursor[i] = excl; }
        carry += tot_s;
        __syncthreads();
    }
    if (t == 0) d_off[n] = carry;
}

// ---------------------------------------------------------------------------
// Scatter + logits
// ---------------------------------------------------------------------------
__global__ void scatter_logits_kernel(const int* __restrict__ idx, int E, int use_atte) {
    int e = blockIdx.x * blockDim.x + threadIdx.x;
    if (e >= E) return;
    int2 rc = ((const int2*)idx)[e];
    int row = rc.x, col = rc.y;
    int pos = atomicAdd(&d_cursor[row], 1);
    d_csrcol[pos] = col;
    const float4* pa = (const float4*)&d_att[(size_t)row * 16];
    const float4* pb = (const float4*)&d_att[(size_t)col * 16 + 8];
    float4 a0 = pa[0], a1 = pa[1];
    float4 b0 = pb[0], b1 = pb[1];
    float lg[8] = {a0.x + b0.x, a0.y + b0.y, a0.z + b0.z, a0.w + b0.w,
                   a1.x + b1.x, a1.y + b1.y, a1.z + b1.z, a1.w + b1.w};
    if (use_atte) {
        const float4* pe = (const float4*)&d_atte[(size_t)e * 8];
        float4 e0 = pe[0], e1 = pe[1];
        lg[0] += e0.x; lg[1] += e0.y; lg[2] += e0.z; lg[3] += e0.w;
        lg[4] += e1.x; lg[5] += e1.y; lg[6] += e1.z; lg[7] += e1.w;
    }
#pragma unroll
    for (int h = 0; h < 8; h++) {
        float u = lg[h];
        u = (u > 0.f) ? u : 0.01f * u;
        lg[h] = u;
        atomicMax(&d_rowmax[(size_t)row * 8 + h], fenc(u));
    }
    *(float4*)&d_logits[(size_t)pos * 8]     = make_float4(lg[0], lg[1], lg[2], lg[3]);
    *(float4*)&d_logits[(size_t)pos * 8 + 4] = make_float4(lg[4], lg[5], lg[6], lg[7]);
}

// ---------------------------------------------------------------------------
// Aggregate: warp per row
// ---------------------------------------------------------------------------
__global__ __launch_bounds__(256)
void aggregate_kernel(float* __restrict__ outp, int M) {
    int warp = (blockIdx.x * blockDim.x + threadIdx.x) >> 5;
    if (warp >= M) return;
    int lane = threadIdx.x & 31;
    int c0 = lane * 4;
    int h = lane >> 2;
    float mx = fdec(d_rowmax[(size_t)warp * 8 + h]);
    int p = d_off[warp], pend = d_off[warp + 1];
    float s = 0.f;
    float4 acc = make_float4(0.f, 0.f, 0.f, 0.f);
    for (; p < pend; ++p) {
        int col = d_csrcol[p];
        float w = __expf(d_logits[(size_t)p * 8 + h] - mx);
        float4 v = *(const float4*)&d_vs[(size_t)col * 256 + c0];
        s += w;
        acc.x += w * v.x; acc.y += w * v.y; acc.z += w * v.z; acc.w += w * v.w;
    }
    float4 sk = *(const float4*)&d_vs[(size_t)warp * 256 + 128 + c0];
    float inv = (s > 0.f) ? (1.f / s) : 0.f;
    float4 o;
    o.x = fmaxf(acc.x * inv + sk.x, 0.f);
    o.y = fmaxf(acc.y * inv + sk.y, 0.f);
    o.z = fmaxf(acc.z * inv + sk.z, 0.f);
    o.w = fmaxf(acc.w * inv + sk.w, 0.f);
    *(float4*)&outp[(size_t)warp * 128 + c0] = o;
}

// ---------------------------------------------------------------------------
// Launch
// ---------------------------------------------------------------------------
extern "C" void kernel_launch(void* const* d_in, const int* in_sizes, int n_in,
                              void* d_out, int out_size) {
    const float* node_fts = (const float*)d_in[0];
    const float* gkt_efts = (const float*)d_in[1];
    const float* hidden   = (const float*)d_in[2];
    const int*   cfg_idx  = (const int*)d_in[3];
    const int*   gkt_idx  = (const int*)d_in[4];
    const float* W_m    = (const float*)d_in[5];
    const float* b_m    = (const float*)d_in[6];
    const float* W_skip = (const float*)d_in[7];
    const float* b_skip = (const float*)d_in[8];
    const float* W_a1   = (const float*)d_in[9];
    const float* b_a1   = (const float*)d_in[10];
    const float* W_a2   = (const float*)d_in[11];
    const float* b_a2   = (const float*)d_in[12];
    const float* W_ae   = (const float*)d_in[13];
    const float* b_ae   = (const float*)d_in[14];
    float* out = (float*)d_out;

    int M  = in_sizes[0] / 128;
    int Ec = in_sizes[3] / 2;
    int Eg = in_sizes[4] / 2;

    float* hid1 = nullptr;
    cudaGetSymbolAddress((void**)&hid1, d_hidden1);

    cudaFuncSetAttribute(gemm_vs_mma_kernel,
                         cudaFuncAttributeMaxDynamicSharedMemorySize, GEMM_SMEM);

    pack_weights_kernel<<<(DIN * NATT + 255) / 256, 256>>>(b_m, b_skip, W_a1, b_a1, W_a2, b_a2);
    pack_weights_bf16_kernel<<<(NVS * DIN + 255) / 256, 256>>>(W_m, W_skip);
    convert_half_kernel<<<(M * 32 + 255) / 256, 256>>>(node_fts, M, 0);   // fts half, once
    edge_att_kernel<<<2048, 256>>>(gkt_efts, W_ae, b_ae, Eg);

    dim3 ggrid((M + 127) / 128, 2);

    // ---- pass 1 (cfg) ----
    convert_half_kernel<<<(M * 32 + 255) / 256, 256>>>(hidden, M, 128);
    gemm_vs_mma_kernel<<<ggrid, 256, GEMM_SMEM>>>(M);
    gemm_att_kernel<<<(M + 127) / 128, 128>>>(node_fts, hidden, M);
    zero_init_kernel<<<(M * 8 + 255) / 256, 256>>>(M);
    count_kernel<<<(Ec + 255) / 256, 256>>>(cfg_idx, Ec);
    scan_kernel<<<1, 1024>>>(M);
    scatter_logits_kernel<<<(Ec + 255) / 256, 256>>>(cfg_idx, Ec, 0);
    aggregate_kernel<<<(M + 7) / 8, 256>>>(hid1, M);

    // ---- pass 2 (gkt) ----
    convert_half_kernel<<<(M * 32 + 255) / 256, 256>>>(hid1, M, 128);
    gemm_vs_mma_kernel<<<ggrid, 256, GEMM_SMEM>>>(M);
    gemm_att_kernel<<<(M + 127) / 128, 128>>>(node_fts, hid1, M);
    zero_init_kernel<<<(M * 8 + 255) / 256, 256>>>(M);
    count_kernel<<<(Eg + 255) / 256, 256>>>(gkt_idx, Eg);
    scan_kernel<<<1, 1024>>>(M);
    scatter_logits_kernel<<<(Eg + 255) / 256, 256>>>(gkt_idx, Eg, 1);
    aggregate_kernel<<<(M + 7) / 8, 256>>>(out, M);
}

// round 4
// speedup vs baseline: 1.4134x; 1.1332x over previous
#include <cuda_runtime.h>
#include <cuda_bf16.h>
#include <cstdint>

// Problem constants (fixed by the dataset)
#define NMAX   50000
#define EMAX   800000
#define OUT_D  128
#define DIN    256
#define NVS    256     // [vals | skip] columns
#define NATT   16      // [att1 | att2] columns

// ---------------------------------------------------------------------------
// Device scratch
// ---------------------------------------------------------------------------
__device__ float    d_bvs[NVS];
__device__ float    d_Watt[DIN * NATT];
__device__ float    d_batt[NATT];
__device__ float    d_atte[EMAX * 8];
__device__ float    d_vs[NMAX * NVS];
__device__ float    d_att[NMAX * NATT];
__device__ float    d_hidden1[NMAX * OUT_D];
__device__ int      d_deg[NMAX];
__device__ int      d_off[NMAX + 1];
__device__ int      d_cursor[NMAX];
__device__ int      d_csrcol[EMAX];
__device__ float    d_logits[EMAX * 8];
__device__ unsigned d_rowmax[NMAX * 8];

// split-bf16 operands for the tensor-core GEMM
__device__ __nv_bfloat16 d_zhi[NMAX * DIN];
__device__ __nv_bfloat16 d_zlo[NMAX * DIN];
__device__ __nv_bfloat16 d_Wbhi[NVS * DIN];
__device__ __nv_bfloat16 d_Wblo[NVS * DIN];

// ---------------------------------------------------------------------------
// Helpers
// ---------------------------------------------------------------------------
__device__ __forceinline__ uint32_t smem_u32(const void* p) {
    uint32_t a;
    asm("{ .reg .u64 t; cvta.to.shared.u64 t, %1; cvt.u32.u64 %0, t; }" : "=r"(a) : "l"(p));
    return a;
}

__device__ __forceinline__ void ldsm4(uint32_t* r, uint32_t addr) {
    asm volatile("ldmatrix.sync.aligned.m8n8.x4.shared.b16 {%0,%1,%2,%3}, [%4];"
                 : "=r"(r[0]), "=r"(r[1]), "=r"(r[2]), "=r"(r[3]) : "r"(addr));
}

__device__ __forceinline__ void mma16816(float* c, const uint32_t* a, uint32_t b0, uint32_t b1) {
    asm volatile("mma.sync.aligned.m16n8k16.row.col.f32.bf16.bf16.f32 "
                 "{%0,%1,%2,%3}, {%4,%5,%6,%7}, {%8,%9}, {%0,%1,%2,%3};"
                 : "+f"(c[0]), "+f"(c[1]), "+f"(c[2]), "+f"(c[3])
                 : "r"(a[0]), "r"(a[1]), "r"(a[2]), "r"(a[3]), "r"(b0), "r"(b1));
}

__device__ __forceinline__ void cpasync16(uint32_t dst, const void* src) {
    asm volatile("cp.async.cg.shared.global [%0], [%1], 16;" :: "r"(dst), "l"(src));
}

__device__ __forceinline__ unsigned fenc(float f) {
    unsigned u = __float_as_uint(f);
    return (u & 0x80000000u) ? ~u : (u | 0x80000000u);
}
__device__ __forceinline__ float fdec(unsigned u) {
    return (u & 0x80000000u) ? __uint_as_float(u & 0x7FFFFFFFu)
                             : __uint_as_float(~u);
}

// ---------------------------------------------------------------------------
// Weight prep
// ---------------------------------------------------------------------------
__global__ void pack_weights_kernel(const float* __restrict__ bm, const float* __restrict__ bsk,
                                    const float* __restrict__ Wa1, const float* __restrict__ ba1,
                                    const float* __restrict__ Wa2, const float* __restrict__ ba2) {
    int i = blockIdx.x * blockDim.x + threadIdx.x;
    if (i < DIN * NATT) {
        int k = i >> 4, j = i & 15;
        d_Watt[i] = (j < 8) ? Wa1[k * 8 + j] : Wa2[k * 8 + (j - 8)];
    }
    if (i < NVS)  d_bvs[i]  = (i < 128) ? bm[i] : bsk[i - 128];
    if (i < NATT) d_batt[i] = (i < 8) ? ba1[i] : ba2[i - 8];
}

__global__ void pack_weights_bf16_kernel(const float* __restrict__ Wm,
                                         const float* __restrict__ Wsk) {
    int i = blockIdx.x * blockDim.x + threadIdx.x;     // i = n*256 + k
    if (i >= NVS * DIN) return;
    int n = i >> 8, k = i & 255;
    float w = (n < 128) ? Wm[k * 128 + n] : Wsk[k * 128 + (n - 128)];
    __nv_bfloat16 hi = __float2bfloat16(w);
    __nv_bfloat16 lo = __float2bfloat16(w - __bfloat162float(hi));
    d_Wbhi[i] = hi;
    d_Wblo[i] = lo;
}

// Convert a 128-wide fp32 node array into half of z (hi/lo split).
__global__ void convert_half_kernel(const float* __restrict__ src, int M, int half_off) {
    int idx = blockIdx.x * blockDim.x + threadIdx.x;
    if (idx >= M * 32) return;
    int row = idx >> 5, c4 = (idx & 31) * 4;
    float4 v = *(const float4*)&src[(size_t)row * 128 + c4];
    __nv_bfloat16 h[4], l[4];
    float f[4] = {v.x, v.y, v.z, v.w};
#pragma unroll
    for (int j = 0; j < 4; j++) {
        h[j] = __float2bfloat16(f[j]);
        l[j] = __float2bfloat16(f[j] - __bfloat162float(h[j]));
    }
    size_t o = (size_t)row * 256 + half_off + c4;
    *(uint2*)&d_zhi[o] = *(uint2*)h;
    *(uint2*)&d_zlo[o] = *(uint2*)l;
}

// ---------------------------------------------------------------------------
// Tensor GEMM via mma.sync (unchanged from R3 — it works)
// ---------------------------------------------------------------------------
#define SSTR 72
#define SROWB (SSTR * 2)
#define OFF_AHI 0
#define OFF_ALO (128 * SROWB)
#define OFF_BHI (2 * 128 * SROWB)
#define OFF_BLO (3 * 128 * SROWB)
#define GEMM_SMEM (4 * 128 * SROWB)

__global__ __launch_bounds__(256, 1)
void gemm_vs_mma_kernel(int M) {
    extern __shared__ char smem[];
    uint32_t sb = smem_u32(smem);
    int t = threadIdx.x, wid = t >> 5, lane = t & 31;
    int warp_m = wid & 1, warp_n = wid >> 1;
    int row0 = blockIdx.x * 128, col0 = blockIdx.y * 128;

    float acc[4][4][4];
#pragma unroll
    for (int a = 0; a < 4; a++)
#pragma unroll
        for (int b = 0; b < 4; b++)
#pragma unroll
            for (int c = 0; c < 4; c++) acc[a][b][c] = 0.f;

    int lrow = lane & 15;
    int lcol = (lane >> 4) * 8;

    for (int kc = 0; kc < 4; kc++) {
        if (kc) __syncthreads();
        int kbase = kc * 64;
#pragma unroll
        for (int i = 0; i < 4; i++) {
            int idx = t + i * 256;
            int r = idx >> 3, k8 = (idx & 7) * 8;
            int grow = row0 + r;
            uint4 ahi = make_uint4(0, 0, 0, 0), alo = ahi;
            if (grow < M) {
                ahi = *(const uint4*)&d_zhi[(size_t)grow * 256 + kbase + k8];
                alo = *(const uint4*)&d_zlo[(size_t)grow * 256 + kbase + k8];
            }
            *(uint4*)(smem + OFF_AHI + r * SROWB + k8 * 2) = ahi;
            *(uint4*)(smem + OFF_ALO + r * SROWB + k8 * 2) = alo;
            int n = col0 + r;
            *(uint4*)(smem + OFF_BHI + r * SROWB + k8 * 2) =
                *(const uint4*)&d_Wbhi[(size_t)n * 256 + kbase + k8];
            *(uint4*)(smem + OFF_BLO + r * SROWB + k8 * 2) =
                *(const uint4*)&d_Wblo[(size_t)n * 256 + kbase + k8];
        }
        __syncthreads();

#pragma unroll
        for (int ks = 0; ks < 4; ks++) {
            int kofs = (ks * 16 + lcol) * 2;
            uint32_t ahi[4][4], alo[4][4];
#pragma unroll
            for (int mi = 0; mi < 4; mi++) {
                uint32_t arow = (uint32_t)(warp_m * 64 + mi * 16 + lrow);
                ldsm4(ahi[mi], sb + OFF_AHI + arow * SROWB + kofs);
                ldsm4(alo[mi], sb + OFF_ALO + arow * SROWB + kofs);
            }
            uint32_t bhi[2][4], blo[2][4];
#pragma unroll
            for (int nj = 0; nj < 2; nj++) {
                uint32_t brow = (uint32_t)(warp_n * 32 + nj * 16 + lrow);
                ldsm4(bhi[nj], sb + OFF_BHI + brow * SROWB + kofs);
                ldsm4(blo[nj], sb + OFF_BLO + brow * SROWB + kofs);
            }
#pragma unroll
            for (int mi = 0; mi < 4; mi++) {
#pragma unroll
                for (int ni = 0; ni < 4; ni++) {
                    int nj = ni >> 1, pr = ni & 1;
                    uint32_t bh0 = bhi[nj][pr], bh1 = bhi[nj][pr + 2];
                    uint32_t bl0 = blo[nj][pr], bl1 = blo[nj][pr + 2];
                    mma16816(acc[mi][ni], ahi[mi], bh0, bh1);
                    mma16816(acc[mi][ni], ahi[mi], bl0, bl1);
                    mma16816(acc[mi][ni], alo[mi], bh0, bh1);
                }
            }
        }
    }

#pragma unroll
    for (int mi = 0; mi < 4; mi++) {
        int rA = row0 + warp_m * 64 + mi * 16 + (lane >> 2);
        int rB = rA + 8;
#pragma unroll
        for (int ni = 0; ni < 4; ni++) {
            int col = col0 + warp_n * 32 + ni * 8 + (lane & 3) * 2;
            float2 bias = *(const float2*)&d_bvs[col];
            if (rA < M) {
                float2 o = make_float2(acc[mi][ni][0] + bias.x, acc[mi][ni][1] + bias.y);
                *(float2*)&d_vs[(size_t)rA * 256 + col] = o;
            }
            if (rB < M) {
                float2 o = make_float2(acc[mi][ni][2] + bias.x, acc[mi][ni][3] + bias.y);
                *(float2*)&d_vs[(size_t)rB * 256 + col] = o;
            }
        }
    }
}

// ---------------------------------------------------------------------------
// Edge-feature attention, cp.async double-buffered tile streamer.
// Tile = 32 edges x 128 floats (16 KB). SMEM row layout: 4 segments of 36
// words (seg s at word s*36) -> banks (4s+i) mod 32, conflict-free for the
// lane split  h = lane&7 (head), s = lane>>3 (k-segment).
// ---------------------------------------------------------------------------
#define EA_TILE 32
#define EA_ROWW 144          // words per smem row (4 segs * 36)

__global__ __launch_bounds__(256)
void edge_att_kernel(const float* __restrict__ efts,
                     const float* __restrict__ Wae,
                     const float* __restrict__ bae, int E, int ntiles) {
    __shared__ float sbuf[2][EA_TILE * EA_ROWW];
    int t = threadIdx.x, lane = t & 31, w = t >> 5;
    int h = lane & 7, s = lane >> 3;

    float wf[32];
#pragma unroll
    for (int i = 0; i < 32; i++) wf[i] = Wae[(s * 32 + i) * 8 + h];
    float b = bae[h];

    uint32_t sb0 = smem_u32(&sbuf[0][0]);
    uint32_t sb1 = smem_u32(&sbuf[1][0]);

    int j = t & 31;                       // float4 index within a row
    int sseg = j >> 3, si = (j & 7) * 4;  // smem segment / word-in-seg
    uint32_t dst_off = (uint32_t)((sseg * 36 + si) * 4);

    int ti = blockIdx.x;
    int tstep = gridDim.x;
    if (ti >= ntiles) return;

    // prefetch tile ti into buffer 0
    {
        int ebase = ti * EA_TILE;
#pragma unroll
        for (int it = 0; it < 4; it++) {
            int r = it * 8 + w;
            int e = ebase + r; if (e >= E) e = E - 1;
            cpasync16(sb0 + (uint32_t)(r * EA_ROWW * 4) + dst_off,
                      efts + (size_t)e * 128 + j * 4);
        }
        asm volatile("cp.async.commit_group;" ::: "memory");
    }

    int bi = 0;
    for (; ti < ntiles; ti += tstep) {
        int tn = ti + tstep;
        if (tn < ntiles) {
            uint32_t sbn = (bi == 0) ? sb1 : sb0;
            int ebase = tn * EA_TILE;
#pragma unroll
            for (int it = 0; it < 4; it++) {
                int r = it * 8 + w;
                int e = ebase + r; if (e >= E) e = E - 1;
                cpasync16(sbn + (uint32_t)(r * EA_ROWW * 4) + dst_off,
                          efts + (size_t)e * 128 + j * 4);
            }
            asm volatile("cp.async.commit_group;" ::: "memory");
            asm volatile("cp.async.wait_group 1;" ::: "memory");
        } else {
            asm volatile("cp.async.wait_group 0;" ::: "memory");
        }
        __syncthreads();

        const float* buf = &sbuf[bi][0];
        int ebase = ti * EA_TILE;
#pragma unroll
        for (int q = 0; q < 4; q++) {
            int r = w * 4 + q;
            int e = ebase + r;
            const float* seg = buf + r * EA_ROWW + s * 36;
            float acc = 0.f;
#pragma unroll
            for (int i = 0; i < 8; i++) {
                float4 v = *(const float4*)(seg + i * 4);
                acc += v.x * wf[i * 4 + 0] + v.y * wf[i * 4 + 1]
                     + v.z * wf[i * 4 + 2] + v.w * wf[i * 4 + 3];
            }
            acc += __shfl_xor_sync(0xffffffffu, acc, 8);
            acc += __shfl_xor_sync(0xffffffffu, acc, 16);
            if (lane < 8 && e < E) d_atte[(size_t)e * 8 + lane] = acc + b;
        }
        __syncthreads();
        bi ^= 1;
    }
}

// ---------------------------------------------------------------------------
// Attention GEMM (small): d_att[M,16] = z @ d_Watt + d_batt  (SIMT)
// ---------------------------------------------------------------------------
__global__ __launch_bounds__(128)
void gemm_att_kernel(const float* __restrict__ fts, const float* __restrict__ hid, int M) {
    __shared__ float Zs[128][33];
    __shared__ float Ws[32][16];
    int t = threadIdx.x;
    int tx = t & 3, ty = t >> 2;
    int row0 = blockIdx.x * 128;
    float acc[4][4];
#pragma unroll
    for (int i = 0; i < 4; i++)
#pragma unroll
        for (int j = 0; j < 4; j++) acc[i][j] = 0.f;

    for (int kb = 0; kb < 256; kb += 32) {
        const float* Z; int zk;
        if (kb < 128) { Z = fts; zk = kb; } else { Z = hid; zk = kb - 128; }
#pragma unroll
        for (int q = 0; q < 8; q++) {
            int idx = q * 128 + t;
            int r = idx >> 3, c4 = (idx & 7) * 4;
            int gr = row0 + r;
            float4 a = make_float4(0.f, 0.f, 0.f, 0.f);
            if (gr < M) a = *(const float4*)&Z[(size_t)gr * 128 + zk + c4];
            Zs[r][c4 + 0] = a.x; Zs[r][c4 + 1] = a.y;
            Zs[r][c4 + 2] = a.z; Zs[r][c4 + 3] = a.w;
        }
        {
            int k = t >> 2, j4 = (t & 3) * 4;
            float4 wv = *(const float4*)&d_Watt[(kb + k) * 16 + j4];
            *(float4*)&Ws[k][j4] = wv;
        }
        __syncthreads();
#pragma unroll
        for (int kk = 0; kk < 32; kk++) {
            float4 bv = *(const float4*)&Ws[kk][tx * 4];
#pragma unroll
            for (int i = 0; i < 4; i++) {
                float a = Zs[ty * 4 + i][kk];
                acc[i][0] += a * bv.x; acc[i][1] += a * bv.y;
                acc[i][2] += a * bv.z; acc[i][3] += a * bv.w;
            }
        }
        __syncthreads();
    }
#pragma unroll
    for (int i = 0; i < 4; i++) {
        int gr = row0 + ty * 4 + i;
        if (gr < M) {
            int j0 = tx * 4;
            float4 o;
            o.x = acc[i][0] + d_batt[j0 + 0];
            o.y = acc[i][1] + d_batt[j0 + 1];
            o.z = acc[i][2] + d_batt[j0 + 2];
            o.w = acc[i][3] + d_batt[j0 + 3];
            *(float4*)&d_att[(size_t)gr * 16 + j0] = o;
        }
    }
}

// ---------------------------------------------------------------------------
// CSR build helpers
// ---------------------------------------------------------------------------
__global__ void zero_init_kernel(int M) {
    int i = blockIdx.x * blockDim.x + threadIdx.x;
    if (i < M) d_deg[i] = 0;
    if (i < M * 8) d_rowmax[i] = 0u;
}

__global__ void count_kernel(const int* __restrict__ idx, int E) {
    int e = blockIdx.x * blockDim.x + threadIdx.x;
    if (e >= E) return;
    int2 rc = ((const int2*)idx)[e];
    atomicAdd(&d_deg[rc.x], 1);
}

__global__ void scan_kernel(int n) {
    __shared__ int wsum[32];
    __shared__ int tot_s;
    int t = threadIdx.x, lane = t & 31, wid = t >> 5;
    int carry = 0;
    for (int base = 0; base < n; base += 1024) {
        int i = base + t;
        int x = (i < n) ? d_deg[i] : 0;
        int v = x;
#pragma unroll
        for (int d = 1; d < 32; d <<= 1) {
            int u = __shfl_up_sync(0xffffffffu, v, d);
            if (lane >= d) v += u;
        }
        if (lane == 31) wsum[wid] = v;
        __syncthreads();
        if (wid == 0) {
            int s = wsum[lane];
            int sv = s;
#pragma unroll
            for (int d = 1; d < 32; d <<= 1) {
                int u = __shfl_up_sync(0xffffffffu, sv, d);
                if (lane >= d) sv += u;
            }
            wsum[lane] = sv - s;
            if (lane == 31) tot_s = sv;
        }
        __syncthreads();
        int excl = carry + wsum[wid] + (v - x);
        if (i < n) { d_off[i] = excl; d_cursor[i] = excl; }
        carry += tot_s;
        __syncthreads();
    }
    if (t == 0) d_off[n] = carry;
}

// ---------------------------------------------------------------------------
// Scatter + logits
// ---------------------------------------------------------------------------
__global__ void scatter_logits_kernel(const int* __restrict__ idx, int E, int use_atte) {
    int e = blockIdx.x * blockDim.x + threadIdx.x;
    if (e >= E) return;
    int2 rc = ((const int2*)idx)[e];
    int row = rc.x, col = rc.y;
    int pos = atomicAdd(&d_cursor[row], 1);
    d_csrcol[pos] = col;
    const float4* pa = (const float4*)&d_att[(size_t)row * 16];
    const float4* pb = (const float4*)&d_att[(size_t)col * 16 + 8];
    float4 a0 = pa[0], a1 = pa[1];
    float4 b0 = pb[0], b1 = pb[1];
    float lg[8] = {a0.x + b0.x, a0.y + b0.y, a0.z + b0.z, a0.w + b0.w,
                   a1.x + b1.x, a1.y + b1.y, a1.z + b1.z, a1.w + b1.w};
    if (use_atte) {
        const float4* pe = (const float4*)&d_atte[(size_t)e * 8];
        float4 e0 = pe[0], e1 = pe[1];
        lg[0] += e0.x; lg[1] += e0.y; lg[2] += e0.z; lg[3] += e0.w;
        lg[4] += e1.x; lg[5] += e1.y; lg[6] += e1.z; lg[7] += e1.w;
    }
#pragma unroll
    for (int h = 0; h < 8; h++) {
        float u = lg[h];
        u = (u > 0.f) ? u : 0.01f * u;
        lg[h] = u;
        atomicMax(&d_rowmax[(size_t)row * 8 + h], fenc(u));
    }
    *(float4*)&d_logits[(size_t)pos * 8]     = make_float4(lg[0], lg[1], lg[2], lg[3]);
    *(float4*)&d_logits[(size_t)pos * 8 + 4] = make_float4(lg[4], lg[5], lg[6], lg[7]);
}

// ---------------------------------------------------------------------------
// Aggregate: warp per row; optionally writes bf16 hi/lo z-half (pass 1).
// ---------------------------------------------------------------------------
__global__ __launch_bounds__(256)
void aggregate_kernel(float* __restrict__ outp, int M, int write_z) {
    int warp = (blockIdx.x * blockDim.x + threadIdx.x) >> 5;
    if (warp >= M) return;
    int lane = threadIdx.x & 31;
    int c0 = lane * 4;
    int h = lane >> 2;
    float mx = fdec(d_rowmax[(size_t)warp * 8 + h]);
    int p = d_off[warp], pend = d_off[warp + 1];
    float s = 0.f;
    float4 acc = make_float4(0.f, 0.f, 0.f, 0.f);
    for (; p < pend; ++p) {
        int col = d_csrcol[p];
        float w = __expf(d_logits[(size_t)p * 8 + h] - mx);
        float4 v = *(const float4*)&d_vs[(size_t)col * 256 + c0];
        s += w;
        acc.x += w * v.x; acc.y += w * v.y; acc.z += w * v.z; acc.w += w * v.w;
    }
    float4 sk = *(const float4*)&d_vs[(size_t)warp * 256 + 128 + c0];
    float inv = (s > 0.f) ? (1.f / s) : 0.f;
    float4 o;
    o.x = fmaxf(acc.x * inv + sk.x, 0.f);
    o.y = fmaxf(acc.y * inv + sk.y, 0.f);
    o.z = fmaxf(acc.z * inv + sk.z, 0.f);
    o.w = fmaxf(acc.w * inv + sk.w, 0.f);
    *(float4*)&outp[(size_t)warp * 128 + c0] = o;
    if (write_z) {
        float f[4] = {o.x, o.y, o.z, o.w};
        __nv_bfloat16 hh[4], ll[4];
#pragma unroll
        for (int jj = 0; jj < 4; jj++) {
            hh[jj] = __float2bfloat16(f[jj]);
            ll[jj] = __float2bfloat16(f[jj] - __bfloat162float(hh[jj]));
        }
        size_t zo = (size_t)warp * 256 + 128 + c0;
        *(uint2*)&d_zhi[zo] = *(uint2*)hh;
        *(uint2*)&d_zlo[zo] = *(uint2*)ll;
    }
}

// ---------------------------------------------------------------------------
// Launch
// ---------------------------------------------------------------------------
extern "C" void kernel_launch(void* const* d_in, const int* in_sizes, int n_in,
                              void* d_out, int out_size) {
    const float* node_fts = (const float*)d_in[0];
    const float* gkt_efts = (const float*)d_in[1];
    const float* hidden   = (const float*)d_in[2];
    const int*   cfg_idx  = (const int*)d_in[3];
    const int*   gkt_idx  = (const int*)d_in[4];
    const float* W_m    = (const float*)d_in[5];
    const float* b_m    = (const float*)d_in[6];
    const float* W_skip = (const float*)d_in[7];
    const float* b_skip = (const float*)d_in[8];
    const float* W_a1   = (const float*)d_in[9];
    const float* b_a1   = (const float*)d_in[10];
    const float* W_a2   = (const float*)d_in[11];
    const float* b_a2   = (const float*)d_in[12];
    const float* W_ae   = (const float*)d_in[13];
    const float* b_ae   = (const float*)d_in[14];
    float* out = (float*)d_out;

    int M  = in_sizes[0] / 128;
    int Ec = in_sizes[3] / 2;
    int Eg = in_sizes[4] / 2;

    float* hid1 = nullptr;
    cudaGetSymbolAddress((void**)&hid1, d_hidden1);

    cudaFuncSetAttribute(gemm_vs_mma_kernel,
                         cudaFuncAttributeMaxDynamicSharedMemorySize, GEMM_SMEM);

    pack_weights_kernel<<<(DIN * NATT + 255) / 256, 256>>>(b_m, b_skip, W_a1, b_a1, W_a2, b_a2);
    pack_weights_bf16_kernel<<<(NVS * DIN + 255) / 256, 256>>>(W_m, W_skip);
    convert_half_kernel<<<(M * 32 + 255) / 256, 256>>>(node_fts, M, 0);
    {
        int ntiles = (Eg + EA_TILE - 1) / EA_TILE;
        edge_att_kernel<<<1776, 256>>>(gkt_efts, W_ae, b_ae, Eg, ntiles);
    }

    dim3 ggrid((M + 127) / 128, 2);

    // ---- pass 1 (cfg) ----
    convert_half_kernel<<<(M * 32 + 255) / 256, 256>>>(hidden, M, 128);
    gemm_vs_mma_kernel<<<ggrid, 256, GEMM_SMEM>>>(M);
    gemm_att_kernel<<<(M + 127) / 128, 128>>>(node_fts, hidden, M);
    zero_init_kernel<<<(M * 8 + 255) / 256, 256>>>(M);
    count_kernel<<<(Ec + 255) / 256, 256>>>(cfg_idx, Ec);
    scan_kernel<<<1, 1024>>>(M);
    scatter_logits_kernel<<<(Ec + 255) / 256, 256>>>(cfg_idx, Ec, 0);
    aggregate_kernel<<<(M + 7) / 8, 256>>>(hid1, M, 1);   // also writes z hi/lo

    // ---- pass 2 (gkt) ----
    gemm_vs_mma_kernel<<<ggrid, 256, GEMM_SMEM>>>(M);
    gemm_att_kernel<<<(M + 127) / 128, 128>>>(node_fts, hid1, M);
    zero_init_kernel<<<(M * 8 + 255) / 256, 256>>>(M);
    count_kernel<<<(Eg + 255) / 256, 256>>>(gkt_idx, Eg);
    scan_kernel<<<1, 1024>>>(M);
    scatter_logits_kernel<<<(Eg + 255) / 256, 256>>>(gkt_idx, Eg, 1);
    aggregate_kernel<<<(M + 7) / 8, 256>>>(out, M, 0);
}

// round 5
// speedup vs baseline: 1.4191x; 1.0041x over previous
#include <cuda_runtime.h>
#include <cuda_bf16.h>
#include <cstdint>

// Problem constants (fixed by the dataset)
#define NMAX   50000
#define EMAX   800000
#define OUT_D  128
#define DIN    256
#define NVS    256     // [vals | skip] columns
#define NATT   16      // [att1 | att2] columns

// ---------------------------------------------------------------------------
// Device scratch
// ---------------------------------------------------------------------------
__device__ float    d_bvs[NVS];
__device__ float    d_Watt[DIN * NATT];
__device__ float    d_batt[NATT];
__device__ float    d_atte[EMAX * 8];
__device__ float    d_vs[NMAX * NVS];
__device__ float    d_att[NMAX * NATT];
__device__ float    d_hidden1[NMAX * OUT_D];
__device__ int      d_deg[NMAX];
__device__ int      d_off[NMAX + 1];
__device__ int      d_cursor[NMAX];
__device__ int      d_csrcol[EMAX];
__device__ float    d_logits[EMAX * 8];
__device__ unsigned d_rowmax[NMAX * 8];

// split-bf16 operands for the tensor-core GEMM
__device__ __nv_bfloat16 d_zhi[NMAX * DIN];
__device__ __nv_bfloat16 d_zlo[NMAX * DIN];
__device__ __nv_bfloat16 d_Wbhi[NVS * DIN];
__device__ __nv_bfloat16 d_Wblo[NVS * DIN];

// ---------------------------------------------------------------------------
// Helpers
// ---------------------------------------------------------------------------
__device__ __forceinline__ uint32_t smem_u32(const void* p) {
    uint32_t a;
    asm("{ .reg .u64 t; cvta.to.shared.u64 t, %1; cvt.u32.u64 %0, t; }" : "=r"(a) : "l"(p));
    return a;
}

__device__ __forceinline__ void ldsm4(uint32_t* r, uint32_t addr) {
    asm volatile("ldmatrix.sync.aligned.m8n8.x4.shared.b16 {%0,%1,%2,%3}, [%4];"
                 : "=r"(r[0]), "=r"(r[1]), "=r"(r[2]), "=r"(r[3]) : "r"(addr));
}

__device__ __forceinline__ void mma16816(float* c, const uint32_t* a, uint32_t b0, uint32_t b1) {
    asm volatile("mma.sync.aligned.m16n8k16.row.col.f32.bf16.bf16.f32 "
                 "{%0,%1,%2,%3}, {%4,%5,%6,%7}, {%8,%9}, {%0,%1,%2,%3};"
                 : "+f"(c[0]), "+f"(c[1]), "+f"(c[2]), "+f"(c[3])
                 : "r"(a[0]), "r"(a[1]), "r"(a[2]), "r"(a[3]), "r"(b0), "r"(b1));
}

__device__ __forceinline__ void cpasync16(uint32_t dst, const void* src) {
    asm volatile("cp.async.cg.shared.global [%0], [%1], 16;" :: "r"(dst), "l"(src));
}

__device__ __forceinline__ unsigned fenc(float f) {
    unsigned u = __float_as_uint(f);
    return (u & 0x80000000u) ? ~u : (u | 0x80000000u);
}
__device__ __forceinline__ float fdec(unsigned u) {
    return (u & 0x80000000u) ? __uint_as_float(u & 0x7FFFFFFFu)
                             : __uint_as_float(~u);
}

// ---------------------------------------------------------------------------
// Weight prep
// ---------------------------------------------------------------------------
__global__ void pack_weights_kernel(const float* __restrict__ bm, const float* __restrict__ bsk,
                                    const float* __restrict__ Wa1, const float* __restrict__ ba1,
                                    const float* __restrict__ Wa2, const float* __restrict__ ba2) {
    int i = blockIdx.x * blockDim.x + threadIdx.x;
    if (i < DIN * NATT) {
        int k = i >> 4, j = i & 15;
        d_Watt[i] = (j < 8) ? Wa1[k * 8 + j] : Wa2[k * 8 + (j - 8)];
    }
    if (i < NVS)  d_bvs[i]  = (i < 128) ? bm[i] : bsk[i - 128];
    if (i < NATT) d_batt[i] = (i < 8) ? ba1[i] : ba2[i - 8];
}

__global__ void pack_weights_bf16_kernel(const float* __restrict__ Wm,
                                         const float* __restrict__ Wsk) {
    int i = blockIdx.x * blockDim.x + threadIdx.x;     // i = n*256 + k
    if (i >= NVS * DIN) return;
    int n = i >> 8, k = i & 255;
    float w = (n < 128) ? Wm[k * 128 + n] : Wsk[k * 128 + (n - 128)];
    __nv_bfloat16 hi = __float2bfloat16(w);
    __nv_bfloat16 lo = __float2bfloat16(w - __bfloat162float(hi));
    d_Wbhi[i] = hi;
    d_Wblo[i] = lo;
}

// Convert a 128-wide fp32 node array into half of z (hi/lo split).
__global__ void convert_half_kernel(const float* __restrict__ src, int M, int half_off) {
    int idx = blockIdx.x * blockDim.x + threadIdx.x;
    if (idx >= M * 32) return;
    int row = idx >> 5, c4 = (idx & 31) * 4;
    float4 v = *(const float4*)&src[(size_t)row * 128 + c4];
    __nv_bfloat16 h[4], l[4];
    float f[4] = {v.x, v.y, v.z, v.w};
#pragma unroll
    for (int j = 0; j < 4; j++) {
        h[j] = __float2bfloat16(f[j]);
        l[j] = __float2bfloat16(f[j] - __bfloat162float(h[j]));
    }
    size_t o = (size_t)row * 256 + half_off + c4;
    *(uint2*)&d_zhi[o] = *(uint2*)h;
    *(uint2*)&d_zlo[o] = *(uint2*)l;
}

// ---------------------------------------------------------------------------
// Tensor GEMM via mma.sync (unchanged from R3 — it works)
// ---------------------------------------------------------------------------
#define SSTR 72
#define SROWB (SSTR * 2)
#define OFF_AHI 0
#define OFF_ALO (128 * SROWB)
#define OFF_BHI (2 * 128 * SROWB)
#define OFF_BLO (3 * 128 * SROWB)
#define GEMM_SMEM (4 * 128 * SROWB)

__global__ __launch_bounds__(256, 1)
void gemm_vs_mma_kernel(int M) {
    extern __shared__ char smem[];
    uint32_t sb = smem_u32(smem);
    int t = threadIdx.x, wid = t >> 5, lane = t & 31;
    int warp_m = wid & 1, warp_n = wid >> 1;
    int row0 = blockIdx.x * 128, col0 = blockIdx.y * 128;

    float acc[4][4][4];
#pragma unroll
    for (int a = 0; a < 4; a++)
#pragma unroll
        for (int b = 0; b < 4; b++)
#pragma unroll
            for (int c = 0; c < 4; c++) acc[a][b][c] = 0.f;

    int lrow = lane & 15;
    int lcol = (lane >> 4) * 8;

    for (int kc = 0; kc < 4; kc++) {
        if (kc) __syncthreads();
        int kbase = kc * 64;
#pragma unroll
        for (int i = 0; i < 4; i++) {
            int idx = t + i * 256;
            int r = idx >> 3, k8 = (idx & 7) * 8;
            int grow = row0 + r;
            uint4 ahi = make_uint4(0, 0, 0, 0), alo = ahi;
            if (grow < M) {
                ahi = *(const uint4*)&d_zhi[(size_t)grow * 256 + kbase + k8];
                alo = *(const uint4*)&d_zlo[(size_t)grow * 256 + kbase + k8];
            }
            *(uint4*)(smem + OFF_AHI + r * SROWB + k8 * 2) = ahi;
            *(uint4*)(smem + OFF_ALO + r * SROWB + k8 * 2) = alo;
            int n = col0 + r;
            *(uint4*)(smem + OFF_BHI + r * SROWB + k8 * 2) =
                *(const uint4*)&d_Wbhi[(size_t)n * 256 + kbase + k8];
            *(uint4*)(smem + OFF_BLO + r * SROWB + k8 * 2) =
                *(const uint4*)&d_Wblo[(size_t)n * 256 + kbase + k8];
        }
        __syncthreads();

#pragma unroll
        for (int ks = 0; ks < 4; ks++) {
            int kofs = (ks * 16 + lcol) * 2;
            uint32_t ahi[4][4], alo[4][4];
#pragma unroll
            for (int mi = 0; mi < 4; mi++) {
                uint32_t arow = (uint32_t)(warp_m * 64 + mi * 16 + lrow);
                ldsm4(ahi[mi], sb + OFF_AHI + arow * SROWB + kofs);
                ldsm4(alo[mi], sb + OFF_ALO + arow * SROWB + kofs);
            }
            uint32_t bhi[2][4], blo[2][4];
#pragma unroll
            for (int nj = 0; nj < 2; nj++) {
                uint32_t brow = (uint32_t)(warp_n * 32 + nj * 16 + lrow);
                ldsm4(bhi[nj], sb + OFF_BHI + brow * SROWB + kofs);
                ldsm4(blo[nj], sb + OFF_BLO + brow * SROWB + kofs);
            }
#pragma unroll
            for (int mi = 0; mi < 4; mi++) {
#pragma unroll
                for (int ni = 0; ni < 4; ni++) {
                    int nj = ni >> 1, pr = ni & 1;
                    uint32_t bh0 = bhi[nj][pr], bh1 = bhi[nj][pr + 2];
                    uint32_t bl0 = blo[nj][pr], bl1 = blo[nj][pr + 2];
                    mma16816(acc[mi][ni], ahi[mi], bh0, bh1);
                    mma16816(acc[mi][ni], ahi[mi], bl0, bl1);
                    mma16816(acc[mi][ni], alo[mi], bh0, bh1);
                }
            }
        }
    }

#pragma unroll
    for (int mi = 0; mi < 4; mi++) {
        int rA = row0 + warp_m * 64 + mi * 16 + (lane >> 2);
        int rB = rA + 8;
#pragma unroll
        for (int ni = 0; ni < 4; ni++) {
            int col = col0 + warp_n * 32 + ni * 8 + (lane & 3) * 2;
            float2 bias = *(const float2*)&d_bvs[col];
            if (rA < M) {
                float2 o = make_float2(acc[mi][ni][0] + bias.x, acc[mi][ni][1] + bias.y);
                *(float2*)&d_vs[(size_t)rA * 256 + col] = o;
            }
            if (rB < M) {
                float2 o = make_float2(acc[mi][ni][2] + bias.x, acc[mi][ni][3] + bias.y);
                *(float2*)&d_vs[(size_t)rB * 256 + col] = o;
            }
        }
    }
}

// ---------------------------------------------------------------------------
// Edge-feature attention, cp.async double-buffered tile streamer.
// Tile = 32 edges x 128 floats (16 KB). SMEM row layout: 4 segments of 36
// words (seg s at word s*36) -> banks (4s+i) mod 32, conflict-free for the
// lane split  h = lane&7 (head), s = lane>>3 (k-segment).
// ---------------------------------------------------------------------------
#define EA_TILE 32
#define EA_ROWW 144          // words per smem row (4 segs * 36)

__global__ __launch_bounds__(256)
void edge_att_kernel(const float* __restrict__ efts,
                     const float* __restrict__ Wae,
                     const float* __restrict__ bae, int E, int ntiles) {
    __shared__ float sbuf[2][EA_TILE * EA_ROWW];
    int t = threadIdx.x, lane = t & 31, w = t >> 5;
    int h = lane & 7, s = lane >> 3;

    float wf[32];
#pragma unroll
    for (int i = 0; i < 32; i++) wf[i] = Wae[(s * 32 + i) * 8 + h];
    float b = bae[h];

    uint32_t sb0 = smem_u32(&sbuf[0][0]);
    uint32_t sb1 = smem_u32(&sbuf[1][0]);

    int j = t & 31;                       // float4 index within a row
    int sseg = j >> 3, si = (j & 7) * 4;  // smem segment / word-in-seg
    uint32_t dst_off = (uint32_t)((sseg * 36 + si) * 4);

    int ti = blockIdx.x;
    int tstep = gridDim.x;
    if (ti >= ntiles) return;

    // prefetch tile ti into buffer 0
    {
        int ebase = ti * EA_TILE;
#pragma unroll
        for (int it = 0; it < 4; it++) {
            int r = it * 8 + w;
            int e = ebase + r; if (e >= E) e = E - 1;
            cpasync16(sb0 + (uint32_t)(r * EA_ROWW * 4) + dst_off,
                      efts + (size_t)e * 128 + j * 4);
        }
        asm volatile("cp.async.commit_group;" ::: "memory");
    }

    int bi = 0;
    for (; ti < ntiles; ti += tstep) {
        int tn = ti + tstep;
        if (tn < ntiles) {
            uint32_t sbn = (bi == 0) ? sb1 : sb0;
            int ebase = tn * EA_TILE;
#pragma unroll
            for (int it = 0; it < 4; it++) {
                int r = it * 8 + w;
                int e = ebase + r; if (e >= E) e = E - 1;
                cpasync16(sbn + (uint32_t)(r * EA_ROWW * 4) + dst_off,
                          efts + (size_t)e * 128 + j * 4);
            }
            asm volatile("cp.async.commit_group;" ::: "memory");
            asm volatile("cp.async.wait_group 1;" ::: "memory");
        } else {
            asm volatile("cp.async.wait_group 0;" ::: "memory");
        }
        __syncthreads();

        const float* buf = &sbuf[bi][0];
        int ebase = ti * EA_TILE;
#pragma unroll
        for (int q = 0; q < 4; q++) {
            int r = w * 4 + q;
            int e = ebase + r;
            const float* seg = buf + r * EA_ROWW + s * 36;
            float acc = 0.f;
#pragma unroll
            for (int i = 0; i < 8; i++) {
                float4 v = *(const float4*)(seg + i * 4);
                acc += v.x * wf[i * 4 + 0] + v.y * wf[i * 4 + 1]
                     + v.z * wf[i * 4 + 2] + v.w * wf[i * 4 + 3];
            }
            acc += __shfl_xor_sync(0xffffffffu, acc, 8);
            acc += __shfl_xor_sync(0xffffffffu, acc, 16);
            if (lane < 8 && e < E) d_atte[(size_t)e * 8 + lane] = acc + b;
        }
        __syncthreads();
        bi ^= 1;
    }
}

// ---------------------------------------------------------------------------
// Attention GEMM (small): d_att[M,16] = z @ d_Watt + d_batt  (SIMT)
// ---------------------------------------------------------------------------
__global__ __launch_bounds__(128)
void gemm_att_kernel(const float* __restrict__ fts, const float* __restrict__ hid, int M) {
    __shared__ float Zs[128][33];
    __shared__ float Ws[32][16];
    int t = threadIdx.x;
    int tx = t & 3, ty = t >> 2;
    int row0 = blockIdx.x * 128;
    float acc[4][4];
#pragma unroll
    for (int i = 0; i < 4; i++)
#pragma unroll
        for (int j = 0; j < 4; j++) acc[i][j] = 0.f;

    for (int kb = 0; kb < 256; kb += 32) {
        const float* Z; int zk;
        if (kb < 128) { Z = fts; zk = kb; } else { Z = hid; zk = kb - 128; }
#pragma unroll
        for (int q = 0; q < 8; q++) {
            int idx = q * 128 + t;
            int r = idx >> 3, c4 = (idx & 7) * 4;
            int gr = row0 + r;
            float4 a = make_float4(0.f, 0.f, 0.f, 0.f);
            if (gr < M) a = *(const float4*)&Z[(size_t)gr * 128 + zk + c4];
            Zs[r][c4 + 0] = a.x; Zs[r][c4 + 1] = a.y;
            Zs[r][c4 + 2] = a.z; Zs[r][c4 + 3] = a.w;
        }
        {
            int k = t >> 2, j4 = (t & 3) * 4;
            float4 wv = *(const float4*)&d_Watt[(kb + k) * 16 + j4];
            *(float4*)&Ws[k][j4] = wv;
        }
        __syncthreads();
#pragma unroll
        for (int kk = 0; kk < 32; kk++) {
            float4 bv = *(const float4*)&Ws[kk][tx * 4];
#pragma unroll
            for (int i = 0; i < 4; i++) {
                float a = Zs[ty * 4 + i][kk];
                acc[i][0] += a * bv.x; acc[i][1] += a * bv.y;
                acc[i][2] += a * bv.z; acc[i][3] += a * bv.w;
            }
        }
        __syncthreads();
    }
#pragma unroll
    for (int i = 0; i < 4; i++) {
        int gr = row0 + ty * 4 + i;
        if (gr < M) {
            int j0 = tx * 4;
            float4 o;
            o.x = acc[i][0] + d_batt[j0 + 0];
            o.y = acc[i][1] + d_batt[j0 + 1];
            o.z = acc[i][2] + d_batt[j0 + 2];
            o.w = acc[i][3] + d_batt[j0 + 3];
            *(float4*)&d_att[(size_t)gr * 16 + j0] = o;
        }
    }
}

// ---------------------------------------------------------------------------
// CSR build helpers
// ---------------------------------------------------------------------------
__global__ void zero_init_kernel(int M) {
    int i = blockIdx.x * blockDim.x + threadIdx.x;
    if (i < M) d_deg[i] = 0;
    if (i < M * 8) d_rowmax[i] = 0u;
}

__global__ void count_kernel(const int* __restrict__ idx, int E) {
    int e = blockIdx.x * blockDim.x + threadIdx.x;
    if (e >= E) return;
    int2 rc = ((const int2*)idx)[e];
    atomicAdd(&d_deg[rc.x], 1);
}

__global__ void scan_kernel(int n) {
    __shared__ int wsum[32];
    __shared__ int tot_s;
    int t = threadIdx.x, lane = t & 31, wid = t >> 5;
    int carry = 0;
    for (int base = 0; base < n; base += 1024) {
        int i = base + t;
        int x = (i < n) ? d_deg[i] : 0;
        int v = x;
#pragma unroll
        for (int d = 1; d < 32; d <<= 1) {
            int u = __shfl_up_sync(0xffffffffu, v, d);
            if (lane >= d) v += u;
        }
        if (lane == 31) wsum[wid] = v;
        __syncthreads();
        if (wid == 0) {
            int s = wsum[lane];
            int sv = s;
#pragma unroll
            for (int d = 1; d < 32; d <<= 1) {
                int u = __shfl_up_sync(0xffffffffu, sv, d);
                if (lane >= d) sv += u;
            }
            wsum[lane] = sv - s;
            if (lane == 31) tot_s = sv;
        }
        __syncthreads();
        int excl = carry + wsum[wid] + (v - x);
        if (i < n) { d_off[i] = excl; d_cursor[i] = excl; }
        carry += tot_s;
        __syncthreads();
    }
    if (t == 0) d_off[n] = carry;
}

// ---------------------------------------------------------------------------
// Scatter + logits
// ---------------------------------------------------------------------------
__global__ void scatter_logits_kernel(const int* __restrict__ idx, int E, int use_atte) {
    int e = blockIdx.x * blockDim.x + threadIdx.x;
    if (e >= E) return;
    int2 rc = ((const int2*)idx)[e];
    int row = rc.x, col = rc.y;
    int pos = atomicAdd(&d_cursor[row], 1);
    d_csrcol[pos] = col;
    const float4* pa = (const float4*)&d_att[(size_t)row * 16];
    const float4* pb = (const float4*)&d_att[(size_t)col * 16 + 8];
    float4 a0 = pa[0], a1 = pa[1];
    float4 b0 = pb[0], b1 = pb[1];
    float lg[8] = {a0.x + b0.x, a0.y + b0.y, a0.z + b0.z, a0.w + b0.w,
                   a1.x + b1.x, a1.y + b1.y, a1.z + b1.z, a1.w + b1.w};
    if (use_atte) {
        const float4* pe = (const float4*)&d_atte[(size_t)e * 8];
        float4 e0 = pe[0], e1 = pe[1];
        lg[0] += e0.x; lg[1] += e0.y; lg[2] += e0.z; lg[3] += e0.w;
        lg[4] += e1.x; lg[5] += e1.y; lg[6] += e1.z; lg[7] += e1.w;
    }
#pragma unroll
    for (int h = 0; h < 8; h++) {
        float u = lg[h];
        u = (u > 0.f) ? u : 0.01f * u;
        lg[h] = u;
        atomicMax(&d_rowmax[(size_t)row * 8 + h], fenc(u));
    }
    *(float4*)&d_logits[(size_t)pos * 8]     = make_float4(lg[0], lg[1], lg[2], lg[3]);
    *(float4*)&d_logits[(size_t)pos * 8 + 4] = make_float4(lg[4], lg[5], lg[6], lg[7]);
}

// ---------------------------------------------------------------------------
// Aggregate: warp per row; optionally writes bf16 hi/lo z-half (pass 1).
// ---------------------------------------------------------------------------
__global__ __launch_bounds__(256)
void aggregate_kernel(float* __restrict__ outp, int M, int write_z) {
    int warp = (blockIdx.x * blockDim.x + threadIdx.x) >> 5;
    if (warp >= M) return;
    int lane = threadIdx.x & 31;
    int c0 = lane * 4;
    int h = lane >> 2;
    float mx = fdec(d_rowmax[(size_t)warp * 8 + h]);
    int p = d_off[warp], pend = d_off[warp + 1];
    float s = 0.f;
    float4 acc = make_float4(0.f, 0.f, 0.f, 0.f);
    for (; p < pend; ++p) {
        int col = d_csrcol[p];
        float w = __expf(d_logits[(size_t)p * 8 + h] - mx);
        float4 v = *(const float4*)&d_vs[(size_t)col * 256 + c0];
        s += w;
        acc.x += w * v.x; acc.y += w * v.y; acc.z += w * v.z; acc.w += w * v.w;
    }
    float4 sk = *(const float4*)&d_vs[(size_t)warp * 256 + 128 + c0];
    float inv = (s > 0.f) ? (1.f / s) : 0.f;
    float4 o;
    o.x = fmaxf(acc.x * inv + sk.x, 0.f);
    o.y = fmaxf(acc.y * inv + sk.y, 0.f);
    o.z = fmaxf(acc.z * inv + sk.z, 0.f);
    o.w = fmaxf(acc.w * inv + sk.w, 0.f);
    *(float4*)&outp[(size_t)warp * 128 + c0] = o;
    if (write_z) {
        float f[4] = {o.x, o.y, o.z, o.w};
        __nv_bfloat16 hh[4], ll[4];
#pragma unroll
        for (int jj = 0; jj < 4; jj++) {
            hh[jj] = __float2bfloat16(f[jj]);
            ll[jj] = __float2bfloat16(f[jj] - __bfloat162float(hh[jj]));
        }
        size_t zo = (size_t)warp * 256 + 128 + c0;
        *(uint2*)&d_zhi[zo] = *(uint2*)hh;
        *(uint2*)&d_zlo[zo] = *(uint2*)ll;
    }
}

// ---------------------------------------------------------------------------
// Launch
// ---------------------------------------------------------------------------
extern "C" void kernel_launch(void* const* d_in, const int* in_sizes, int n_in,
                              void* d_out, int out_size) {
    const float* node_fts = (const float*)d_in[0];
    const float* gkt_efts = (const float*)d_in[1];
    const float* hidden   = (const float*)d_in[2];
    const int*   cfg_idx  = (const int*)d_in[3];
    const int*   gkt_idx  = (const int*)d_in[4];
    const float* W_m    = (const float*)d_in[5];
    const float* b_m    = (const float*)d_in[6];
    const float* W_skip = (const float*)d_in[7];
    const float* b_skip = (const float*)d_in[8];
    const float* W_a1   = (const float*)d_in[9];
    const float* b_a1   = (const float*)d_in[10];
    const float* W_a2   = (const float*)d_in[11];
    const float* b_a2   = (const float*)d_in[12];
    const float* W_ae   = (const float*)d_in[13];
    const float* b_ae   = (const float*)d_in[14];
    float* out = (float*)d_out;

    int M  = in_sizes[0] / 128;
    int Ec = in_sizes[3] / 2;
    int Eg = in_sizes[4] / 2;

    float* hid1 = nullptr;
    cudaGetSymbolAddress((void**)&hid1, d_hidden1);

    cudaFuncSetAttribute(gemm_vs_mma_kernel,
                         cudaFuncAttributeMaxDynamicSharedMemorySize, GEMM_SMEM);

    pack_weights_kernel<<<(DIN * NATT + 255) / 256, 256>>>(b_m, b_skip, W_a1, b_a1, W_a2, b_a2);
    pack_weights_bf16_kernel<<<(NVS * DIN + 255) / 256, 256>>>(W_m, W_skip);
    convert_half_kernel<<<(M * 32 + 255) / 256, 256>>>(node_fts, M, 0);
    {
        int ntiles = (Eg + EA_TILE - 1) / EA_TILE;
        edge_att_kernel<<<1776, 256>>>(gkt_efts, W_ae, b_ae, Eg, ntiles);
    }

    dim3 ggrid((M + 127) / 128, 2);

    // ---- pass 1 (cfg) ----
    convert_half_kernel<<<(M * 32 + 255) / 256, 256>>>(hidden, M, 128);
    gemm_vs_mma_kernel<<<ggrid, 256, GEMM_SMEM>>>(M);
    gemm_att_kernel<<<(M + 127) / 128, 128>>>(node_fts, hidden, M);
    zero_init_kernel<<<(M * 8 + 255) / 256, 256>>>(M);
    count_kernel<<<(Ec + 255) / 256, 256>>>(cfg_idx, Ec);
    scan_kernel<<<1, 1024>>>(M);
    scatter_logits_kernel<<<(Ec + 255) / 256, 256>>>(cfg_idx, Ec, 0);
    aggregate_kernel<<<(M + 7) / 8, 256>>>(hid1, M, 1);   // also writes z hi/lo

    // ---- pass 2 (gkt) ----
    gemm_vs_mma_kernel<<<ggrid, 256, GEMM_SMEM>>>(M);
    gemm_att_kernel<<<(M + 127) / 128, 128>>>(node_fts, hid1, M);
    zero_init_kernel<<<(M * 8 + 255) / 256, 256>>>(M);
    count_kernel<<<(Eg + 255) / 256, 256>>>(gkt_idx, Eg);
    scan_kernel<<<1, 1024>>>(M);
    scatter_logits_kernel<<<(Eg + 255) / 256, 256>>>(gkt_idx, Eg, 1);
    aggregate_kernel<<<(M + 7) / 8, 256>>>(out, M, 0);
}

// round 6
// speedup vs baseline: 1.5260x; 1.0753x over previous
#include <cuda_runtime.h>
#include <cuda_bf16.h>
#include <cstdint>

// Problem constants (fixed by the dataset)
#define NMAX   50000
#define EMAX   800000
#define OUT_D  128
#define DIN    256
#define NVS    256
#define NATT   16

// ---------------------------------------------------------------------------
// Device scratch
// ---------------------------------------------------------------------------
__device__ float    d_bvs[NVS];
__device__ float    d_batt[NATT];
__device__ float    d_atte[EMAX * 8];
__device__ float    d_vs[NMAX * NVS];
__device__ float    d_att[NMAX * NATT];
__device__ float    d_hidden1[NMAX * OUT_D];
__device__ int      d_deg[NMAX];
__device__ int      d_off[NMAX + 1];
__device__ int      d_cursor[NMAX];
__device__ int      d_csrcol[EMAX];
__device__ float    d_logits[EMAX * 8];
__device__ unsigned d_rowmax[NMAX * 8];

// split-bf16 operands for the tensor-core GEMMs
__device__ __nv_bfloat16 d_zhi[NMAX * DIN];
__device__ __nv_bfloat16 d_zlo[NMAX * DIN];
__device__ __nv_bfloat16 d_Wbhi[NVS * DIN];
__device__ __nv_bfloat16 d_Wblo[NVS * DIN];
__device__ __nv_bfloat16 d_Wathi[NATT * DIN];   // att weights, [n][k]
__device__ __nv_bfloat16 d_Watlo[NATT * DIN];

// ---------------------------------------------------------------------------
// Helpers
// ---------------------------------------------------------------------------
__device__ __forceinline__ uint32_t smem_u32(const void* p) {
    uint32_t a;
    asm("{ .reg .u64 t; cvta.to.shared.u64 t, %1; cvt.u32.u64 %0, t; }" : "=r"(a) : "l"(p));
    return a;
}

__device__ __forceinline__ void ldsm4(uint32_t* r, uint32_t addr) {
    asm volatile("ldmatrix.sync.aligned.m8n8.x4.shared.b16 {%0,%1,%2,%3}, [%4];"
                 : "=r"(r[0]), "=r"(r[1]), "=r"(r[2]), "=r"(r[3]) : "r"(addr));
}

__device__ __forceinline__ void mma16816(float* c, const uint32_t* a, uint32_t b0, uint32_t b1) {
    asm volatile("mma.sync.aligned.m16n8k16.row.col.f32.bf16.bf16.f32 "
                 "{%0,%1,%2,%3}, {%4,%5,%6,%7}, {%8,%9}, {%0,%1,%2,%3};"
                 : "+f"(c[0]), "+f"(c[1]), "+f"(c[2]), "+f"(c[3])
                 : "r"(a[0]), "r"(a[1]), "r"(a[2]), "r"(a[3]), "r"(b0), "r"(b1));
}

__device__ __forceinline__ void cpasync16(uint32_t dst, const void* src) {
    asm volatile("cp.async.cg.shared.global [%0], [%1], 16;" :: "r"(dst), "l"(src));
}

__device__ __forceinline__ unsigned fenc(float f) {
    unsigned u = __float_as_uint(f);
    return (u & 0x80000000u) ? ~u : (u | 0x80000000u);
}
__device__ __forceinline__ float fdec(unsigned u) {
    return (u & 0x80000000u) ? __uint_as_float(u & 0x7FFFFFFFu)
                             : __uint_as_float(~u);
}

// ---------------------------------------------------------------------------
// Weight prep
// ---------------------------------------------------------------------------
__global__ void pack_bias_kernel(const float* __restrict__ bm, const float* __restrict__ bsk,
                                 const float* __restrict__ ba1, const float* __restrict__ ba2) {
    int i = blockIdx.x * blockDim.x + threadIdx.x;
    if (i < NVS)  d_bvs[i]  = (i < 128) ? bm[i] : bsk[i - 128];
    if (i < NATT) d_batt[i] = (i < 8) ? ba1[i] : ba2[i - 8];
}

__global__ void pack_weights_bf16_kernel(const float* __restrict__ Wm,
                                         const float* __restrict__ Wsk,
                                         const float* __restrict__ Wa1,
                                         const float* __restrict__ Wa2) {
    int i = blockIdx.x * blockDim.x + threadIdx.x;     // i = n*256 + k
    if (i < NVS * DIN) {
        int n = i >> 8, k = i & 255;
        float w = (n < 128) ? Wm[k * 128 + n] : Wsk[k * 128 + (n - 128)];
        __nv_bfloat16 hi = __float2bfloat16(w);
        __nv_bfloat16 lo = __float2bfloat16(w - __bfloat162float(hi));
        d_Wbhi[i] = hi;
        d_Wblo[i] = lo;
    }
    if (i < NATT * DIN) {
        int n = i >> 8, k = i & 255;
        float w = (n < 8) ? Wa1[k * 8 + n] : Wa2[k * 8 + (n - 8)];
        __nv_bfloat16 hi = __float2bfloat16(w);
        __nv_bfloat16 lo = __float2bfloat16(w - __bfloat162float(hi));
        d_Wathi[i] = hi;
        d_Watlo[i] = lo;
    }
}

// Convert a 128-wide fp32 node array into half of z (hi/lo split).
__global__ void convert_half_kernel(const float* __restrict__ src, int M, int half_off) {
    int idx = blockIdx.x * blockDim.x + threadIdx.x;
    if (idx >= M * 32) return;
    int row = idx >> 5, c4 = (idx & 31) * 4;
    float4 v = *(const float4*)&src[(size_t)row * 128 + c4];
    __nv_bfloat16 h[4], l[4];
    float f[4] = {v.x, v.y, v.z, v.w};
#pragma unroll
    for (int j = 0; j < 4; j++) {
        h[j] = __float2bfloat16(f[j]);
        l[j] = __float2bfloat16(f[j] - __bfloat162float(h[j]));
    }
    size_t o = (size_t)row * 256 + half_off + c4;
    *(uint2*)&d_zhi[o] = *(uint2*)h;
    *(uint2*)&d_zlo[o] = *(uint2*)l;
}

// ---------------------------------------------------------------------------
// Tensor GEMM via mma.sync, now also producing d_att (fused att GEMM).
// CTA tile 128x128 (grid.y = col half), 256 threads = 2x4 warps (m2 x n4),
// warp tile 64x32, BK=64 x 4 chunks. blockIdx.y==0 CTAs with warp_n<2 also
// accumulate att[128x16] from the same A fragments + a small Watt tile.
// ---------------------------------------------------------------------------
#define SSTR 72
#define SROWB (SSTR * 2)
#define OFF_AHI 0
#define OFF_ALO (128 * SROWB)
#define OFF_BHI (2 * 128 * SROWB)
#define OFF_BLO (3 * 128 * SROWB)
#define OFF_WHI (4 * 128 * SROWB)
#define OFF_WLO (OFF_WHI + 16 * SROWB)
#define GEMM_SMEM (OFF_WLO + 16 * SROWB)

__global__ __launch_bounds__(256, 1)
void gemm_vs_mma_kernel(int M) {
    extern __shared__ char smem[];
    uint32_t sb = smem_u32(smem);
    int t = threadIdx.x, wid = t >> 5, lane = t & 31;
    int warp_m = wid & 1, warp_n = wid >> 1;
    int row0 = blockIdx.x * 128, col0 = blockIdx.y * 128;
    bool blk_att = (blockIdx.y == 0);
    bool do_att = blk_att && (warp_n < 2);

    float acc[4][4][4];
#pragma unroll
    for (int a = 0; a < 4; a++)
#pragma unroll
        for (int b = 0; b < 4; b++)
#pragma unroll
            for (int c = 0; c < 4; c++) acc[a][b][c] = 0.f;
    float acc_att[4][4];
#pragma unroll
    for (int a = 0; a < 4; a++)
#pragma unroll
        for (int c = 0; c < 4; c++) acc_att[a][c] = 0.f;

    int lrow = lane & 15;
    int lcol = (lane >> 4) * 8;

    for (int kc = 0; kc < 4; kc++) {
        if (kc) __syncthreads();
        int kbase = kc * 64;
#pragma unroll
        for (int i = 0; i < 4; i++) {
            int idx = t + i * 256;
            int r = idx >> 3, k8 = (idx & 7) * 8;
            int grow = row0 + r;
            uint4 ahi = make_uint4(0, 0, 0, 0), alo = ahi;
            if (grow < M) {
                ahi = *(const uint4*)&d_zhi[(size_t)grow * 256 + kbase + k8];
                alo = *(const uint4*)&d_zlo[(size_t)grow * 256 + kbase + k8];
            }
            *(uint4*)(smem + OFF_AHI + r * SROWB + k8 * 2) = ahi;
            *(uint4*)(smem + OFF_ALO + r * SROWB + k8 * 2) = alo;
            int n = col0 + r;
            *(uint4*)(smem + OFF_BHI + r * SROWB + k8 * 2) =
                *(const uint4*)&d_Wbhi[(size_t)n * 256 + kbase + k8];
            *(uint4*)(smem + OFF_BLO + r * SROWB + k8 * 2) =
                *(const uint4*)&d_Wblo[(size_t)n * 256 + kbase + k8];
        }
        if (blk_att) {
            // Watt tile: 16 rows x 64 halves, hi (t<128) / lo (t>=128)
            int r = (t >> 3) & 15, k8 = (t & 7) * 8;
            const __nv_bfloat16* src = (t < 128) ? d_Wathi : d_Watlo;
            int off = (t < 128) ? OFF_WHI : OFF_WLO;
            *(uint4*)(smem + off + r * SROWB + k8 * 2) =
                *(const uint4*)&src[(size_t)r * 256 + kbase + k8];
        }
        __syncthreads();

#pragma unroll
        for (int ks = 0; ks < 4; ks++) {
            int kofs = (ks * 16 + lcol) * 2;
            uint32_t ahi[4][4], alo[4][4];
#pragma unroll
            for (int mi = 0; mi < 4; mi++) {
                uint32_t arow = (uint32_t)(warp_m * 64 + mi * 16 + lrow);
                ldsm4(ahi[mi], sb + OFF_AHI + arow * SROWB + kofs);
                ldsm4(alo[mi], sb + OFF_ALO + arow * SROWB + kofs);
            }
            uint32_t bhi[2][4], blo[2][4];
#pragma unroll
            for (int nj = 0; nj < 2; nj++) {
                uint32_t brow = (uint32_t)(warp_n * 32 + nj * 16 + lrow);
                ldsm4(bhi[nj], sb + OFF_BHI + brow * SROWB + kofs);
                ldsm4(blo[nj], sb + OFF_BLO + brow * SROWB + kofs);
            }
#pragma unroll
            for (int mi = 0; mi < 4; mi++) {
#pragma unroll
                for (int ni = 0; ni < 4; ni++) {
                    int nj = ni >> 1, pr = ni & 1;
                    uint32_t bh0 = bhi[nj][pr], bh1 = bhi[nj][pr + 2];
                    uint32_t bl0 = blo[nj][pr], bl1 = blo[nj][pr + 2];
                    mma16816(acc[mi][ni], ahi[mi], bh0, bh1);
                    mma16816(acc[mi][ni], ahi[mi], bl0, bl1);
                    mma16816(acc[mi][ni], alo[mi], bh0, bh1);
                }
            }
            if (do_att) {
                uint32_t whi[4], wlo[4];
                ldsm4(whi, sb + OFF_WHI + (uint32_t)lrow * SROWB + kofs);
                ldsm4(wlo, sb + OFF_WLO + (uint32_t)lrow * SROWB + kofs);
                uint32_t wh0 = whi[warp_n], wh1 = whi[warp_n + 2];
                uint32_t wl0 = wlo[warp_n], wl1 = wlo[warp_n + 2];
#pragma unroll
                for (int mi = 0; mi < 4; mi++) {
                    mma16816(acc_att[mi], ahi[mi], wh0, wh1);
                    mma16816(acc_att[mi], ahi[mi], wl0, wl1);
                    mma16816(acc_att[mi], alo[mi], wh0, wh1);
                }
            }
        }
    }

#pragma unroll
    for (int mi = 0; mi < 4; mi++) {
        int rA = row0 + warp_m * 64 + mi * 16 + (lane >> 2);
        int rB = rA + 8;
#pragma unroll
        for (int ni = 0; ni < 4; ni++) {
            int col = col0 + warp_n * 32 + ni * 8 + (lane & 3) * 2;
            float2 bias = *(const float2*)&d_bvs[col];
            if (rA < M) {
                float2 o = make_float2(acc[mi][ni][0] + bias.x, acc[mi][ni][1] + bias.y);
                *(float2*)&d_vs[(size_t)rA * 256 + col] = o;
            }
            if (rB < M) {
                float2 o = make_float2(acc[mi][ni][2] + bias.x, acc[mi][ni][3] + bias.y);
                *(float2*)&d_vs[(size_t)rB * 256 + col] = o;
            }
        }
        if (do_att) {
            int col = warp_n * 8 + (lane & 3) * 2;
            float2 bias = *(const float2*)&d_batt[col];
            if (rA < M) {
                float2 o = make_float2(acc_att[mi][0] + bias.x, acc_att[mi][1] + bias.y);
                *(float2*)&d_att[(size_t)rA * 16 + col] = o;
            }
            if (rB < M) {
                float2 o = make_float2(acc_att[mi][2] + bias.x, acc_att[mi][3] + bias.y);
                *(float2*)&d_att[(size_t)rB * 16 + col] = o;
            }
        }
    }
}

// ---------------------------------------------------------------------------
// Edge-feature attention, cp.async double-buffered tile streamer.
// min 4 blocks/SM (register cap 64) to raise memory-level parallelism.
// ---------------------------------------------------------------------------
#define EA_TILE 32
#define EA_ROWW 144

__global__ __launch_bounds__(256, 4)
void edge_att_kernel(const float* __restrict__ efts,
                     const float* __restrict__ Wae,
                     const float* __restrict__ bae, int E, int ntiles) {
    __shared__ float sbuf[2][EA_TILE * EA_ROWW];
    int t = threadIdx.x, lane = t & 31, w = t >> 5;
    int h = lane & 7, s = lane >> 3;

    float wf[32];
#pragma unroll
    for (int i = 0; i < 32; i++) wf[i] = Wae[(s * 32 + i) * 8 + h];
    float b = bae[h];

    uint32_t sb0 = smem_u32(&sbuf[0][0]);
    uint32_t sb1 = smem_u32(&sbuf[1][0]);

    int j = t & 31;
    int sseg = j >> 3, si = (j & 7) * 4;
    uint32_t dst_off = (uint32_t)((sseg * 36 + si) * 4);

    int ti = blockIdx.x;
    int tstep = gridDim.x;
    if (ti >= ntiles) return;

    {
        int ebase = ti * EA_TILE;
#pragma unroll
        for (int it = 0; it < 4; it++) {
            int r = it * 8 + w;
            int e = ebase + r; if (e >= E) e = E - 1;
            cpasync16(sb0 + (uint32_t)(r * EA_ROWW * 4) + dst_off,
                      efts + (size_t)e * 128 + j * 4);
        }
        asm volatile("cp.async.commit_group;" ::: "memory");
    }

    int bi = 0;
    for (; ti < ntiles; ti += tstep) {
        int tn = ti + tstep;
        if (tn < ntiles) {
            uint32_t sbn = (bi == 0) ? sb1 : sb0;
            int ebase = tn * EA_TILE;
#pragma unroll
            for (int it = 0; it < 4; it++) {
                int r = it * 8 + w;
                int e = ebase + r; if (e >= E) e = E - 1;
                cpasync16(sbn + (uint32_t)(r * EA_ROWW * 4) + dst_off,
                          efts + (size_t)e * 128 + j * 4);
            }
            asm volatile("cp.async.commit_group;" ::: "memory");
            asm volatile("cp.async.wait_group 1;" ::: "memory");
        } else {
            asm volatile("cp.async.wait_group 0;" ::: "memory");
        }
        __syncthreads();

        const float* buf = &sbuf[bi][0];
        int ebase = ti * EA_TILE;
#pragma unroll
        for (int q = 0; q < 4; q++) {
            int r = w * 4 + q;
            int e = ebase + r;
            const float* seg = buf + r * EA_ROWW + s * 36;
            float acc = 0.f;
#pragma unroll
            for (int i = 0; i < 8; i++) {
                float4 v = *(const float4*)(seg + i * 4);
                acc += v.x * wf[i * 4 + 0] + v.y * wf[i * 4 + 1]
                     + v.z * wf[i * 4 + 2] + v.w * wf[i * 4 + 3];
            }
            acc += __shfl_xor_sync(0xffffffffu, acc, 8);
            acc += __shfl_xor_sync(0xffffffffu, acc, 16);
            if (lane < 8 && e < E) d_atte[(size_t)e * 8 + lane] = acc + b;
        }
        __syncthreads();
        bi ^= 1;
    }
}

// ---------------------------------------------------------------------------
// CSR build helpers
// ---------------------------------------------------------------------------
__global__ void zero_init_kernel(int M) {
    int i = blockIdx.x * blockDim.x + threadIdx.x;
    if (i < M) d_deg[i] = 0;
    if (i < M * 8) d_rowmax[i] = 0u;
}

__global__ void count_kernel(const int* __restrict__ idx, int E) {
    int e = blockIdx.x * blockDim.x + threadIdx.x;
    if (e >= E) return;
    int2 rc = ((const int2*)idx)[e];
    atomicAdd(&d_deg[rc.x], 1);
}

__global__ void scan_kernel(int n) {
    __shared__ int wsum[32];
    __shared__ int tot_s;
    int t = threadIdx.x, lane = t & 31, wid = t >> 5;
    int carry = 0;
    for (int base = 0; base < n; base += 1024) {
        int i = base + t;
        int x = (i < n) ? d_deg[i] : 0;
        int v = x;
#pragma unroll
        for (int d = 1; d < 32; d <<= 1) {
            int u = __shfl_up_sync(0xffffffffu, v, d);
            if (lane >= d) v += u;
        }
        if (lane == 31) wsum[wid] = v;
        __syncthreads();
        if (wid == 0) {
            int s = wsum[lane];
            int sv = s;
#pragma unroll
            for (int d = 1; d < 32; d <<= 1) {
                int u = __shfl_up_sync(0xffffffffu, sv, d);
                if (lane >= d) sv += u;
            }
            wsum[lane] = sv - s;
            if (lane == 31) tot_s = sv;
        }
        __syncthreads();
        int excl = carry + wsum[wid] + (v - x);
        if (i < n) { d_off[i] = excl; d_cursor[i] = excl; }
        carry += tot_s;
        __syncthreads();
    }
    if (t == 0) d_off[n] = carry;
}

// ---------------------------------------------------------------------------
// Scatter + logits
// ---------------------------------------------------------------------------
__global__ void scatter_logits_kernel(const int* __restrict__ idx, int E, int use_atte) {
    int e = blockIdx.x * blockDim.x + threadIdx.x;
    if (e >= E) return;
    int2 rc = ((const int2*)idx)[e];
    int row = rc.x, col = rc.y;
    int pos = atomicAdd(&d_cursor[row], 1);
    d_csrcol[pos] = col;
    const float4* pa = (const float4*)&d_att[(size_t)row * 16];
    const float4* pb = (const float4*)&d_att[(size_t)col * 16 + 8];
    float4 a0 = pa[0], a1 = pa[1];
    float4 b0 = pb[0], b1 = pb[1];
    float lg[8] = {a0.x + b0.x, a0.y + b0.y, a0.z + b0.z, a0.w + b0.w,
                   a1.x + b1.x, a1.y + b1.y, a1.z + b1.z, a1.w + b1.w};
    if (use_atte) {
        const float4* pe = (const float4*)&d_atte[(size_t)e * 8];
        float4 e0 = pe[0], e1 = pe[1];
        lg[0] += e0.x; lg[1] += e0.y; lg[2] += e0.z; lg[3] += e0.w;
        lg[4] += e1.x; lg[5] += e1.y; lg[6] += e1.z; lg[7] += e1.w;
    }
#pragma unroll
    for (int h = 0; h < 8; h++) {
        float u = lg[h];
        u = (u > 0.f) ? u : 0.01f * u;
        lg[h] = u;
        atomicMax(&d_rowmax[(size_t)row * 8 + h], fenc(u));
    }
    *(float4*)&d_logits[(size_t)pos * 8]     = make_float4(lg[0], lg[1], lg[2], lg[3]);
    *(float4*)&d_logits[(size_t)pos * 8 + 4] = make_float4(lg[4], lg[5], lg[6], lg[7]);
}

// ---------------------------------------------------------------------------
// Aggregate: warp per row; optionally writes bf16 hi/lo z-half (pass 1).
// ---------------------------------------------------------------------------
__global__ __launch_bounds__(256)
void aggregate_kernel(float* __restrict__ outp, int M, int write_z) {
    int warp = (blockIdx.x * blockDim.x + threadIdx.x) >> 5;
    if (warp >= M) return;
    int lane = threadIdx.x & 31;
    int c0 = lane * 4;
    int h = lane >> 2;
    float mx = fdec(d_rowmax[(size_t)warp * 8 + h]);
    int p = d_off[warp], pend = d_off[warp + 1];
    float s = 0.f;
    float4 acc = make_float4(0.f, 0.f, 0.f, 0.f);
    for (; p < pend; ++p) {
        int col = d_csrcol[p];
        float w = __expf(d_logits[(size_t)p * 8 + h] - mx);
        float4 v = *(const float4*)&d_vs[(size_t)col * 256 + c0];
        s += w;
        acc.x += w * v.x; acc.y += w * v.y; acc.z += w * v.z; acc.w += w * v.w;
    }
    float4 sk = *(const float4*)&d_vs[(size_t)warp * 256 + 128 + c0];
    float inv = (s > 0.f) ? (1.f / s) : 0.f;
    float4 o;
    o.x = fmaxf(acc.x * inv + sk.x, 0.f);
    o.y = fmaxf(acc.y * inv + sk.y, 0.f);
    o.z = fmaxf(acc.z * inv + sk.z, 0.f);
    o.w = fmaxf(acc.w * inv + sk.w, 0.f);
    *(float4*)&outp[(size_t)warp * 128 + c0] = o;
    if (write_z) {
        float f[4] = {o.x, o.y, o.z, o.w};
        __nv_bfloat16 hh[4], ll[4];
#pragma unroll
        for (int jj = 0; jj < 4; jj++) {
            hh[jj] = __float2bfloat16(f[jj]);
            ll[jj] = __float2bfloat16(f[jj] - __bfloat162float(hh[jj]));
        }
        size_t zo = (size_t)warp * 256 + 128 + c0;
        *(uint2*)&d_zhi[zo] = *(uint2*)hh;
        *(uint2*)&d_zlo[zo] = *(uint2*)ll;
    }
}

// ---------------------------------------------------------------------------
// Launch
// ---------------------------------------------------------------------------
extern "C" void kernel_launch(void* const* d_in, const int* in_sizes, int n_in,
                              void* d_out, int out_size) {
    const float* node_fts = (const float*)d_in[0];
    const float* gkt_efts = (const float*)d_in[1];
    const float* hidden   = (const float*)d_in[2];
    const int*   cfg_idx  = (const int*)d_in[3];
    const int*   gkt_idx  = (const int*)d_in[4];
    const float* W_m    = (const float*)d_in[5];
    const float* b_m    = (const float*)d_in[6];
    const float* W_skip = (const float*)d_in[7];
    const float* b_skip = (const float*)d_in[8];
    const float* W_a1   = (const float*)d_in[9];
    const float* b_a1   = (const float*)d_in[10];
    const float* W_a2   = (const float*)d_in[11];
    const float* b_a2   = (const float*)d_in[12];
    const float* W_ae   = (const float*)d_in[13];
    const float* b_ae   = (const float*)d_in[14];
    float* out = (float*)d_out;

    int M  = in_sizes[0] / 128;
    int Ec = in_sizes[3] / 2;
    int Eg = in_sizes[4] / 2;

    float* hid1 = nullptr;
    cudaGetSymbolAddress((void**)&hid1, d_hidden1);

    cudaFuncSetAttribute(gemm_vs_mma_kernel,
                         cudaFuncAttributeMaxDynamicSharedMemorySize, GEMM_SMEM);

    pack_bias_kernel<<<1, 256>>>(b_m, b_skip, b_a1, b_a2);
    pack_weights_bf16_kernel<<<(NVS * DIN + 255) / 256, 256>>>(W_m, W_skip, W_a1, W_a2);
    convert_half_kernel<<<(M * 32 + 255) / 256, 256>>>(node_fts, M, 0);
    {
        int ntiles = (Eg + EA_TILE - 1) / EA_TILE;
        edge_att_kernel<<<1776, 256>>>(gkt_efts, W_ae, b_ae, Eg, ntiles);
    }

    dim3 ggrid((M + 127) / 128, 2);

    // ---- pass 1 (cfg) ----
    convert_half_kernel<<<(M * 32 + 255) / 256, 256>>>(hidden, M, 128);
    gemm_vs_mma_kernel<<<ggrid, 256, GEMM_SMEM>>>(M);    // vs + att fused
    zero_init_kernel<<<(M * 8 + 255) / 256, 256>>>(M);
    count_kernel<<<(Ec + 255) / 256, 256>>>(cfg_idx, Ec);
    scan_kernel<<<1, 1024>>>(M);
    scatter_logits_kernel<<<(Ec + 255) / 256, 256>>>(cfg_idx, Ec, 0);
    aggregate_kernel<<<(M + 7) / 8, 256>>>(hid1, M, 1);

    // ---- pass 2 (gkt) ----
    gemm_vs_mma_kernel<<<ggrid, 256, GEMM_SMEM>>>(M);    // vs + att fused
    zero_init_kernel<<<(M * 8 + 255) / 256, 256>>>(M);
    count_kernel<<<(Eg + 255) / 256, 256>>>(gkt_idx, Eg);
    scan_kernel<<<1, 1024>>>(M);
    scatter_logits_kernel<<<(Eg + 255) / 256, 256>>>(gkt_idx, Eg, 1);
    aggregate_kernel<<<(M + 7) / 8, 256>>>(out, M, 0);
}

// round 7
// speedup vs baseline: 1.5315x; 1.0036x over previous
#include <cuda_runtime.h>
#include <cuda_bf16.h>
#include <cstdint>

// Problem constants (fixed by the dataset)
#define NMAX   50000
#define EMAX   800000
#define OUT_D  128
#define DIN    256
#define NVS    256
#define NATT   16

// ---------------------------------------------------------------------------
// Device scratch
// ---------------------------------------------------------------------------
__device__ float    d_bvs[NVS];
__device__ float    d_batt[NATT];
__device__ float    d_atte[EMAX * 8];
__device__ float    d_vs[NMAX * NVS];
__device__ float    d_att[NMAX * NATT];
__device__ float    d_hidden1[NMAX * OUT_D];
__device__ int      d_deg[NMAX];
__device__ int      d_off[NMAX + 1];
__device__ int      d_cursor[NMAX];
__device__ int      d_csrcol[EMAX];
__device__ float    d_logits[EMAX * 8];
__device__ unsigned d_rowmax[NMAX * 8];

// split-bf16 operands for the tensor-core GEMMs
__device__ __nv_bfloat16 d_zhi[NMAX * DIN];
__device__ __nv_bfloat16 d_zlo[NMAX * DIN];
__device__ __nv_bfloat16 d_Wbhi[NVS * DIN];
__device__ __nv_bfloat16 d_Wblo[NVS * DIN];
__device__ __nv_bfloat16 d_Wathi[NATT * DIN];   // att weights, [n][k]
__device__ __nv_bfloat16 d_Watlo[NATT * DIN];

// ---------------------------------------------------------------------------
// Helpers
// ---------------------------------------------------------------------------
__device__ __forceinline__ uint32_t smem_u32(const void* p) {
    uint32_t a;
    asm("{ .reg .u64 t; cvta.to.shared.u64 t, %1; cvt.u32.u64 %0, t; }" : "=r"(a) : "l"(p));
    return a;
}

__device__ __forceinline__ void ldsm4(uint32_t* r, uint32_t addr) {
    asm volatile("ldmatrix.sync.aligned.m8n8.x4.shared.b16 {%0,%1,%2,%3}, [%4];"
                 : "=r"(r[0]), "=r"(r[1]), "=r"(r[2]), "=r"(r[3]) : "r"(addr));
}

__device__ __forceinline__ void mma16816(float* c, const uint32_t* a, uint32_t b0, uint32_t b1) {
    asm volatile("mma.sync.aligned.m16n8k16.row.col.f32.bf16.bf16.f32 "
                 "{%0,%1,%2,%3}, {%4,%5,%6,%7}, {%8,%9}, {%0,%1,%2,%3};"
                 : "+f"(c[0]), "+f"(c[1]), "+f"(c[2]), "+f"(c[3])
                 : "r"(a[0]), "r"(a[1]), "r"(a[2]), "r"(a[3]), "r"(b0), "r"(b1));
}

__device__ __forceinline__ void cpasync16(uint32_t dst, const void* src) {
    asm volatile("cp.async.cg.shared.global [%0], [%1], 16;" :: "r"(dst), "l"(src));
}

__device__ __forceinline__ unsigned fenc(float f) {
    unsigned u = __float_as_uint(f);
    return (u & 0x80000000u) ? ~u : (u | 0x80000000u);
}
__device__ __forceinline__ float fdec(unsigned u) {
    return (u & 0x80000000u) ? __uint_as_float(u & 0x7FFFFFFFu)
                             : __uint_as_float(~u);
}

// ---------------------------------------------------------------------------
// Weight prep
// ---------------------------------------------------------------------------
__global__ void pack_bias_kernel(const float* __restrict__ bm, const float* __restrict__ bsk,
                                 const float* __restrict__ ba1, const float* __restrict__ ba2) {
    int i = blockIdx.x * blockDim.x + threadIdx.x;
    if (i < NVS)  d_bvs[i]  = (i < 128) ? bm[i] : bsk[i - 128];
    if (i < NATT) d_batt[i] = (i < 8) ? ba1[i] : ba2[i - 8];
}

__global__ void pack_weights_bf16_kernel(const float* __restrict__ Wm,
                                         const float* __restrict__ Wsk,
                                         const float* __restrict__ Wa1,
                                         const float* __restrict__ Wa2) {
    int i = blockIdx.x * blockDim.x + threadIdx.x;     // i = n*256 + k
    if (i < NVS * DIN) {
        int n = i >> 8, k = i & 255;
        float w = (n < 128) ? Wm[k * 128 + n] : Wsk[k * 128 + (n - 128)];
        __nv_bfloat16 hi = __float2bfloat16(w);
        __nv_bfloat16 lo = __float2bfloat16(w - __bfloat162float(hi));
        d_Wbhi[i] = hi;
        d_Wblo[i] = lo;
    }
    if (i < NATT * DIN) {
        int n = i >> 8, k = i & 255;
        float w = (n < 8) ? Wa1[k * 8 + n] : Wa2[k * 8 + (n - 8)];
        __nv_bfloat16 hi = __float2bfloat16(w);
        __nv_bfloat16 lo = __float2bfloat16(w - __bfloat162float(hi));
        d_Wathi[i] = hi;
        d_Watlo[i] = lo;
    }
}

// Convert a 128-wide fp32 node array into half of z (hi/lo split).
__global__ void convert_half_kernel(const float* __restrict__ src, int M, int half_off) {
    int idx = blockIdx.x * blockDim.x + threadIdx.x;
    if (idx >= M * 32) return;
    int row = idx >> 5, c4 = (idx & 31) * 4;
    float4 v = *(const float4*)&src[(size_t)row * 128 + c4];
    __nv_bfloat16 h[4], l[4];
    float f[4] = {v.x, v.y, v.z, v.w};
#pragma unroll
    for (int j = 0; j < 4; j++) {
        h[j] = __float2bfloat16(f[j]);
        l[j] = __float2bfloat16(f[j] - __bfloat162float(h[j]));
    }
    size_t o = (size_t)row * 256 + half_off + c4;
    *(uint2*)&d_zhi[o] = *(uint2*)h;
    *(uint2*)&d_zlo[o] = *(uint2*)l;
}

// ---------------------------------------------------------------------------
// Tensor GEMM via mma.sync, now also producing d_att (fused att GEMM).
// CTA tile 128x128 (grid.y = col half), 256 threads = 2x4 warps (m2 x n4),
// warp tile 64x32, BK=64 x 4 chunks. blockIdx.y==0 CTAs with warp_n<2 also
// accumulate att[128x16] from the same A fragments + a small Watt tile.
// ---------------------------------------------------------------------------
#define SSTR 72
#define SROWB (SSTR * 2)
#define OFF_AHI 0
#define OFF_ALO (128 * SROWB)
#define OFF_BHI (2 * 128 * SROWB)
#define OFF_BLO (3 * 128 * SROWB)
#define OFF_WHI (4 * 128 * SROWB)
#define OFF_WLO (OFF_WHI + 16 * SROWB)
#define GEMM_SMEM (OFF_WLO + 16 * SROWB)

__global__ __launch_bounds__(256, 1)
void gemm_vs_mma_kernel(int M) {
    extern __shared__ char smem[];
    uint32_t sb = smem_u32(smem);
    int t = threadIdx.x, wid = t >> 5, lane = t & 31;
    int warp_m = wid & 1, warp_n = wid >> 1;
    int row0 = blockIdx.x * 128, col0 = blockIdx.y * 128;
    bool blk_att = (blockIdx.y == 0);
    bool do_att = blk_att && (warp_n < 2);

    float acc[4][4][4];
#pragma unroll
    for (int a = 0; a < 4; a++)
#pragma unroll
        for (int b = 0; b < 4; b++)
#pragma unroll
            for (int c = 0; c < 4; c++) acc[a][b][c] = 0.f;
    float acc_att[4][4];
#pragma unroll
    for (int a = 0; a < 4; a++)
#pragma unroll
        for (int c = 0; c < 4; c++) acc_att[a][c] = 0.f;

    int lrow = lane & 15;
    int lcol = (lane >> 4) * 8;

    for (int kc = 0; kc < 4; kc++) {
        if (kc) __syncthreads();
        int kbase = kc * 64;
#pragma unroll
        for (int i = 0; i < 4; i++) {
            int idx = t + i * 256;
            int r = idx >> 3, k8 = (idx & 7) * 8;
            int grow = row0 + r;
            uint4 ahi = make_uint4(0, 0, 0, 0), alo = ahi;
            if (grow < M) {
                ahi = *(const uint4*)&d_zhi[(size_t)grow * 256 + kbase + k8];
                alo = *(const uint4*)&d_zlo[(size_t)grow * 256 + kbase + k8];
            }
            *(uint4*)(smem + OFF_AHI + r * SROWB + k8 * 2) = ahi;
            *(uint4*)(smem + OFF_ALO + r * SROWB + k8 * 2) = alo;
            int n = col0 + r;
            *(uint4*)(smem + OFF_BHI + r * SROWB + k8 * 2) =
                *(const uint4*)&d_Wbhi[(size_t)n * 256 + kbase + k8];
            *(uint4*)(smem + OFF_BLO + r * SROWB + k8 * 2) =
                *(const uint4*)&d_Wblo[(size_t)n * 256 + kbase + k8];
        }
        if (blk_att) {
            // Watt tile: 16 rows x 64 halves, hi (t<128) / lo (t>=128)
            int r = (t >> 3) & 15, k8 = (t & 7) * 8;
            const __nv_bfloat16* src = (t < 128) ? d_Wathi : d_Watlo;
            int off = (t < 128) ? OFF_WHI : OFF_WLO;
            *(uint4*)(smem + off + r * SROWB + k8 * 2) =
                *(const uint4*)&src[(size_t)r * 256 + kbase + k8];
        }
        __syncthreads();

#pragma unroll
        for (int ks = 0; ks < 4; ks++) {
            int kofs = (ks * 16 + lcol) * 2;
            uint32_t ahi[4][4], alo[4][4];
#pragma unroll
            for (int mi = 0; mi < 4; mi++) {
                uint32_t arow = (uint32_t)(warp_m * 64 + mi * 16 + lrow);
                ldsm4(ahi[mi], sb + OFF_AHI + arow * SROWB + kofs);
                ldsm4(alo[mi], sb + OFF_ALO + arow * SROWB + kofs);
            }
            uint32_t bhi[2][4], blo[2][4];
#pragma unroll
            for (int nj = 0; nj < 2; nj++) {
                uint32_t brow = (uint32_t)(warp_n * 32 + nj * 16 + lrow);
                ldsm4(bhi[nj], sb + OFF_BHI + brow * SROWB + kofs);
                ldsm4(blo[nj], sb + OFF_BLO + brow * SROWB + kofs);
            }
#pragma unroll
            for (int mi = 0; mi < 4; mi++) {
#pragma unroll
                for (int ni = 0; ni < 4; ni++) {
                    int nj = ni >> 1, pr = ni & 1;
                    uint32_t bh0 = bhi[nj][pr], bh1 = bhi[nj][pr + 2];
                    uint32_t bl0 = blo[nj][pr], bl1 = blo[nj][pr + 2];
                    mma16816(acc[mi][ni], ahi[mi], bh0, bh1);
                    mma16816(acc[mi][ni], ahi[mi], bl0, bl1);
                    mma16816(acc[mi][ni], alo[mi], bh0, bh1);
                }
            }
            if (do_att) {
                uint32_t whi[4], wlo[4];
                ldsm4(whi, sb + OFF_WHI + (uint32_t)lrow * SROWB + kofs);
                ldsm4(wlo, sb + OFF_WLO + (uint32_t)lrow * SROWB + kofs);
                uint32_t wh0 = whi[warp_n], wh1 = whi[warp_n + 2];
                uint32_t wl0 = wlo[warp_n], wl1 = wlo[warp_n + 2];
#pragma unroll
                for (int mi = 0; mi < 4; mi++) {
                    mma16816(acc_att[mi], ahi[mi], wh0, wh1);
                    mma16816(acc_att[mi], ahi[mi], wl0, wl1);
                    mma16816(acc_att[mi], alo[mi], wh0, wh1);
                }
            }
        }
    }

#pragma unroll
    for (int mi = 0; mi < 4; mi++) {
        int rA = row0 + warp_m * 64 + mi * 16 + (lane >> 2);
        int rB = rA + 8;
#pragma unroll
        for (int ni = 0; ni < 4; ni++) {
            int col = col0 + warp_n * 32 + ni * 8 + (lane & 3) * 2;
            float2 bias = *(const float2*)&d_bvs[col];
            if (rA < M) {
                float2 o = make_float2(acc[mi][ni][0] + bias.x, acc[mi][ni][1] + bias.y);
                *(float2*)&d_vs[(size_t)rA * 256 + col] = o;
            }
            if (rB < M) {
                float2 o = make_float2(acc[mi][ni][2] + bias.x, acc[mi][ni][3] + bias.y);
                *(float2*)&d_vs[(size_t)rB * 256 + col] = o;
            }
        }
        if (do_att) {
            int col = warp_n * 8 + (lane & 3) * 2;
            float2 bias = *(const float2*)&d_batt[col];
            if (rA < M) {
                float2 o = make_float2(acc_att[mi][0] + bias.x, acc_att[mi][1] + bias.y);
                *(float2*)&d_att[(size_t)rA * 16 + col] = o;
            }
            if (rB < M) {
                float2 o = make_float2(acc_att[mi][2] + bias.x, acc_att[mi][3] + bias.y);
                *(float2*)&d_att[(size_t)rB * 16 + col] = o;
            }
        }
    }
}

// ---------------------------------------------------------------------------
// Edge-feature attention, cp.async double-buffered tile streamer.
// min 4 blocks/SM (register cap 64) to raise memory-level parallelism.
// ---------------------------------------------------------------------------
#define EA_TILE 32
#define EA_ROWW 144

__global__ __launch_bounds__(256, 4)
void edge_att_kernel(const float* __restrict__ efts,
                     const float* __restrict__ Wae,
                     const float* __restrict__ bae, int E, int ntiles) {
    __shared__ float sbuf[2][EA_TILE * EA_ROWW];
    int t = threadIdx.x, lane = t & 31, w = t >> 5;
    int h = lane & 7, s = lane >> 3;

    float wf[32];
#pragma unroll
    for (int i = 0; i < 32; i++) wf[i] = Wae[(s * 32 + i) * 8 + h];
    float b = bae[h];

    uint32_t sb0 = smem_u32(&sbuf[0][0]);
    uint32_t sb1 = smem_u32(&sbuf[1][0]);

    int j = t & 31;
    int sseg = j >> 3, si = (j & 7) * 4;
    uint32_t dst_off = (uint32_t)((sseg * 36 + si) * 4);

    int ti = blockIdx.x;
    int tstep = gridDim.x;
    if (ti >= ntiles) return;

    {
        int ebase = ti * EA_TILE;
#pragma unroll
        for (int it = 0; it < 4; it++) {
            int r = it * 8 + w;
            int e = ebase + r; if (e >= E) e = E - 1;
            cpasync16(sb0 + (uint32_t)(r * EA_ROWW * 4) + dst_off,
                      efts + (size_t)e * 128 + j * 4);
        }
        asm volatile("cp.async.commit_group;" ::: "memory");
    }

    int bi = 0;
    for (; ti < ntiles; ti += tstep) {
        int tn = ti + tstep;
        if (tn < ntiles) {
            uint32_t sbn = (bi == 0) ? sb1 : sb0;
            int ebase = tn * EA_TILE;
#pragma unroll
            for (int it = 0; it < 4; it++) {
                int r = it * 8 + w;
                int e = ebase + r; if (e >= E) e = E - 1;
                cpasync16(sbn + (uint32_t)(r * EA_ROWW * 4) + dst_off,
                          efts + (size_t)e * 128 + j * 4);
            }
            asm volatile("cp.async.commit_group;" ::: "memory");
            asm volatile("cp.async.wait_group 1;" ::: "memory");
        } else {
            asm volatile("cp.async.wait_group 0;" ::: "memory");
        }
        __syncthreads();

        const float* buf = &sbuf[bi][0];
        int ebase = ti * EA_TILE;
#pragma unroll
        for (int q = 0; q < 4; q++) {
            int r = w * 4 + q;
            int e = ebase + r;
            const float* seg = buf + r * EA_ROWW + s * 36;
            float acc = 0.f;
#pragma unroll
            for (int i = 0; i < 8; i++) {
                float4 v = *(const float4*)(seg + i * 4);
                acc += v.x * wf[i * 4 + 0] + v.y * wf[i * 4 + 1]
                     + v.z * wf[i * 4 + 2] + v.w * wf[i * 4 + 3];
            }
            acc += __shfl_xor_sync(0xffffffffu, acc, 8);
            acc += __shfl_xor_sync(0xffffffffu, acc, 16);
            if (lane < 8 && e < E) d_atte[(size_t)e * 8 + lane] = acc + b;
        }
        __syncthreads();
        bi ^= 1;
    }
}

// ---------------------------------------------------------------------------
// CSR build helpers
// ---------------------------------------------------------------------------
__global__ void zero_init_kernel(int M) {
    int i = blockIdx.x * blockDim.x + threadIdx.x;
    if (i < M) d_deg[i] = 0;
    if (i < M * 8) d_rowmax[i] = 0u;
}

__global__ void count_kernel(const int* __restrict__ idx, int E) {
    int e = blockIdx.x * blockDim.x + threadIdx.x;
    if (e >= E) return;
    int2 rc = ((const int2*)idx)[e];
    atomicAdd(&d_deg[rc.x], 1);
}

__global__ void scan_kernel(int n) {
    __shared__ int wsum[32];
    __shared__ int tot_s;
    int t = threadIdx.x, lane = t & 31, wid = t >> 5;
    int carry = 0;
    for (int base = 0; base < n; base += 1024) {
        int i = base + t;
        int x = (i < n) ? d_deg[i] : 0;
        int v = x;
#pragma unroll
        for (int d = 1; d < 32; d <<= 1) {
            int u = __shfl_up_sync(0xffffffffu, v, d);
            if (lane >= d) v += u;
        }
        if (lane == 31) wsum[wid] = v;
        __syncthreads();
        if (wid == 0) {
            int s = wsum[lane];
            int sv = s;
#pragma unroll
            for (int d = 1; d < 32; d <<= 1) {
                int u = __shfl_up_sync(0xffffffffu, sv, d);
                if (lane >= d) sv += u;
            }
            wsum[lane] = sv - s;
            if (lane == 31) tot_s = sv;
        }
        __syncthreads();
        int excl = carry + wsum[wid] + (v - x);
        if (i < n) { d_off[i] = excl; d_cursor[i] = excl; }
        carry += tot_s;
        __syncthreads();
    }
    if (t == 0) d_off[n] = carry;
}

// ---------------------------------------------------------------------------
// Scatter + logits
// ---------------------------------------------------------------------------
__global__ void scatter_logits_kernel(const int* __restrict__ idx, int E, int use_atte) {
    int e = blockIdx.x * blockDim.x + threadIdx.x;
    if (e >= E) return;
    int2 rc = ((const int2*)idx)[e];
    int row = rc.x, col = rc.y;
    int pos = atomicAdd(&d_cursor[row], 1);
    d_csrcol[pos] = col;
    const float4* pa = (const float4*)&d_att[(size_t)row * 16];
    const float4* pb = (const float4*)&d_att[(size_t)col * 16 + 8];
    float4 a0 = pa[0], a1 = pa[1];
    float4 b0 = pb[0], b1 = pb[1];
    float lg[8] = {a0.x + b0.x, a0.y + b0.y, a0.z + b0.z, a0.w + b0.w,
                   a1.x + b1.x, a1.y + b1.y, a1.z + b1.z, a1.w + b1.w};
    if (use_atte) {
        const float4* pe = (const float4*)&d_atte[(size_t)e * 8];
        float4 e0 = pe[0], e1 = pe[1];
        lg[0] += e0.x; lg[1] += e0.y; lg[2] += e0.z; lg[3] += e0.w;
        lg[4] += e1.x; lg[5] += e1.y; lg[6] += e1.z; lg[7] += e1.w;
    }
#pragma unroll
    for (int h = 0; h < 8; h++) {
        float u = lg[h];
        u = (u > 0.f) ? u : 0.01f * u;
        lg[h] = u;
        atomicMax(&d_rowmax[(size_t)row * 8 + h], fenc(u));
    }
    *(float4*)&d_logits[(size_t)pos * 8]     = make_float4(lg[0], lg[1], lg[2], lg[3]);
    *(float4*)&d_logits[(size_t)pos * 8 + 4] = make_float4(lg[4], lg[5], lg[6], lg[7]);
}

// ---------------------------------------------------------------------------
// Aggregate: warp per row; optionally writes bf16 hi/lo z-half (pass 1).
// ---------------------------------------------------------------------------
__global__ __launch_bounds__(256)
void aggregate_kernel(float* __restrict__ outp, int M, int write_z) {
    int warp = (blockIdx.x * blockDim.x + threadIdx.x) >> 5;
    if (warp >= M) return;
    int lane = threadIdx.x & 31;
    int c0 = lane * 4;
    int h = lane >> 2;
    float mx = fdec(d_rowmax[(size_t)warp * 8 + h]);
    int p = d_off[warp], pend = d_off[warp + 1];
    float s = 0.f;
    float4 acc = make_float4(0.f, 0.f, 0.f, 0.f);
    for (; p < pend; ++p) {
        int col = d_csrcol[p];
        float w = __expf(d_logits[(size_t)p * 8 + h] - mx);
        float4 v = *(const float4*)&d_vs[(size_t)col * 256 + c0];
        s += w;
        acc.x += w * v.x; acc.y += w * v.y; acc.z += w * v.z; acc.w += w * v.w;
    }
    float4 sk = *(const float4*)&d_vs[(size_t)warp * 256 + 128 + c0];
    float inv = (s > 0.f) ? (1.f / s) : 0.f;
    float4 o;
    o.x = fmaxf(acc.x * inv + sk.x, 0.f);
    o.y = fmaxf(acc.y * inv + sk.y, 0.f);
    o.z = fmaxf(acc.z * inv + sk.z, 0.f);
    o.w = fmaxf(acc.w * inv + sk.w, 0.f);
    *(float4*)&outp[(size_t)warp * 128 + c0] = o;
    if (write_z) {
        float f[4] = {o.x, o.y, o.z, o.w};
        __nv_bfloat16 hh[4], ll[4];
#pragma unroll
        for (int jj = 0; jj < 4; jj++) {
            hh[jj] = __float2bfloat16(f[jj]);
            ll[jj] = __float2bfloat16(f[jj] - __bfloat162float(hh[jj]));
        }
        size_t zo = (size_t)warp * 256 + 128 + c0;
        *(uint2*)&d_zhi[zo] = *(uint2*)hh;
        *(uint2*)&d_zlo[zo] = *(uint2*)ll;
    }
}

// ---------------------------------------------------------------------------
// Launch
// ---------------------------------------------------------------------------
extern "C" void kernel_launch(void* const* d_in, const int* in_sizes, int n_in,
                              void* d_out, int out_size) {
    const float* node_fts = (const float*)d_in[0];
    const float* gkt_efts = (const float*)d_in[1];
    const float* hidden   = (const float*)d_in[2];
    const int*   cfg_idx  = (const int*)d_in[3];
    const int*   gkt_idx  = (const int*)d_in[4];
    const float* W_m    = (const float*)d_in[5];
    const float* b_m    = (const float*)d_in[6];
    const float* W_skip = (const float*)d_in[7];
    const float* b_skip = (const float*)d_in[8];
    const float* W_a1   = (const float*)d_in[9];
    const float* b_a1   = (const float*)d_in[10];
    const float* W_a2   = (const float*)d_in[11];
    const float* b_a2   = (const float*)d_in[12];
    const float* W_ae   = (const float*)d_in[13];
    const float* b_ae   = (const float*)d_in[14];
    float* out = (float*)d_out;

    int M  = in_sizes[0] / 128;
    int Ec = in_sizes[3] / 2;
    int Eg = in_sizes[4] / 2;

    float* hid1 = nullptr;
    cudaGetSymbolAddress((void**)&hid1, d_hidden1);

    cudaFuncSetAttribute(gemm_vs_mma_kernel,
                         cudaFuncAttributeMaxDynamicSharedMemorySize, GEMM_SMEM);

    pack_bias_kernel<<<1, 256>>>(b_m, b_skip, b_a1, b_a2);
    pack_weights_bf16_kernel<<<(NVS * DIN + 255) / 256, 256>>>(W_m, W_skip, W_a1, W_a2);
    convert_half_kernel<<<(M * 32 + 255) / 256, 256>>>(node_fts, M, 0);
    {
        int ntiles = (Eg + EA_TILE - 1) / EA_TILE;
        edge_att_kernel<<<1776, 256>>>(gkt_efts, W_ae, b_ae, Eg, ntiles);
    }

    dim3 ggrid((M + 127) / 128, 2);

    // ---- pass 1 (cfg) ----
    convert_half_kernel<<<(M * 32 + 255) / 256, 256>>>(hidden, M, 128);
    gemm_vs_mma_kernel<<<ggrid, 256, GEMM_SMEM>>>(M);    // vs + att fused
    zero_init_kernel<<<(M * 8 + 255) / 256, 256>>>(M);
    count_kernel<<<(Ec + 255) / 256, 256>>>(cfg_idx, Ec);
    scan_kernel<<<1, 1024>>>(M);
    scatter_logits_kernel<<<(Ec + 255) / 256, 256>>>(cfg_idx, Ec, 0);
    aggregate_kernel<<<(M + 7) / 8, 256>>>(hid1, M, 1);

    // ---- pass 2 (gkt) ----
    gemm_vs_mma_kernel<<<ggrid, 256, GEMM_SMEM>>>(M);    // vs + att fused
    zero_init_kernel<<<(M * 8 + 255) / 256, 256>>>(M);
    count_kernel<<<(Eg + 255) / 256, 256>>>(gkt_idx, Eg);
    scan_kernel<<<1, 1024>>>(M);
    scatter_logits_kernel<<<(Eg + 255) / 256, 256>>>(gkt_idx, Eg, 1);
    aggregate_kernel<<<(M + 7) / 8, 256>>>(out, M, 0);
}